// round 13
// baseline (speedup 1.0000x reference)
#include <cuda_runtime.h>
#include <cuda_bf16.h>
#include <cuda_fp16.h>
#include <math.h>
#include <stdint.h>

// Problem constants
constexpr int NN = 8192;
constexpr int DD = 1024;
constexpr float BD = 819.2f;   // 0.1 * n
constexpr float BU = 7372.8f;  // 0.9 * n
constexpr float INSCALE = 256.0f;            // int8 quantization scale
constexpr float ACCSCALE = 1.0f / 65536.0f;  // 1/(256*256)

// ---------------- device scratch (static, allocation-free) ----------------
__device__ uint8_t g_P0[(size_t)NN * NN];    // 64 MB, e4m3 of exp(L - 1)
__device__ uint8_t g_P0T[(size_t)NN * NN];   // 64 MB, transpose of g_P0
__device__ int8_t g_A8[(size_t)NN * DD];     // 8 MB, int8 of 256*A
__device__ int8_t g_B8[(size_t)NN * DD];     // 8 MB, int8 of 256*B
__device__ float g_c[NN], g_c2[NN];
__device__ float g_r[NN], g_r2[NN];
__device__ float g_u[NN], g_u2[NN];   // row sums; reused as CE S accumulators
__device__ float g_s[NN], g_s2[NN];   // col sums
__device__ float g_diag[NN], g_diag2[NN];
__device__ float g_sums[1];

// ---------------- fp8 helpers ----------------
__device__ __forceinline__ unsigned short f32x2_to_e4m3x2(float lo, float hi) {
    unsigned short r;
    asm("cvt.rn.satfinite.e4m3x2.f32 %0, %1, %2;" : "=h"(r) : "f"(hi), "f"(lo));
    return r;
}
__device__ __forceinline__ __half2 e4m3x2_to_h2(unsigned short s) {
    uint32_t h;
    asm("cvt.rn.f16x2.e4m3x2 %0, %1;" : "=r"(h) : "h"(s));
    return *reinterpret_cast<__half2*>(&h);
}
__device__ __forceinline__ float e4m3_byte_to_f32(uint8_t b) {
    return __low2float(e4m3x2_to_h2((unsigned short)b));
}
__device__ __forceinline__ __half2 shfl_down_h2(__half2 v, int o) {
    uint32_t u = *reinterpret_cast<uint32_t*>(&v);
    u = __shfl_down_sync(0xffffffffu, u, o);
    return *reinterpret_cast<__half2*>(&u);
}
__device__ __forceinline__ uint32_t ldg_u32_nc(const uint8_t* p) {
    uint32_t u;
    asm volatile("ld.global.nc.u32 %0, [%1];" : "=r"(u) : "l"(p));
    return u;
}
__device__ __forceinline__ uint2 ldg_u64_nc(const uint8_t* p) {
    uint2 u;
    asm volatile("ld.global.nc.v2.u32 {%0,%1}, [%2];"
                 : "=r"(u.x), "=r"(u.y) : "l"(p));
    return u;
}

// ---------------- init ----------------
__global__ void init_kernel() {
    int i = blockIdx.x * blockDim.x + threadIdx.x;
    if (i < NN) {
        g_c[i] = 1.0f; g_c2[i] = 1.0f;
        g_u[i] = 0.0f; g_u2[i] = 0.0f;
        g_s[i] = 0.0f; g_s2[i] = 0.0f;
    }
    if (i == 0) g_sums[0] = 0.0f;
}

// ---------------- fp32 -> int8 convert (scale 256) ----------------
__device__ __forceinline__ uint32_t quant4(float4 v) {
    int i0 = __float2int_rn(fminf(fmaxf(v.x * INSCALE, -127.f), 127.f));
    int i1 = __float2int_rn(fminf(fmaxf(v.y * INSCALE, -127.f), 127.f));
    int i2 = __float2int_rn(fminf(fmaxf(v.z * INSCALE, -127.f), 127.f));
    int i3 = __float2int_rn(fminf(fmaxf(v.w * INSCALE, -127.f), 127.f));
    return (uint32_t)(i0 & 255) | ((uint32_t)(i1 & 255) << 8) |
           ((uint32_t)(i2 & 255) << 16) | ((uint32_t)(i3 & 255) << 24);
}
__global__ __launch_bounds__(256) void convert_kernel(
    const float* __restrict__ A, const float* __restrict__ B) {
    int i = blockIdx.x * blockDim.x + threadIdx.x;  // float4 index
    const int n4 = NN * DD / 4;
    if (i < n4) {
        reinterpret_cast<uint32_t*>(g_A8)[i] =
            quant4(reinterpret_cast<const float4*>(A)[i]);
        reinterpret_cast<uint32_t*>(g_B8)[i] =
            quant4(reinterpret_cast<const float4*>(B)[i]);
    }
}

// ---------------- int8 tensor-core GEMM: P0 = e4m3(exp(acc/65536 - 1)) ------
constexpr int KSTG = 128;                 // K elements (bytes) per stage
constexpr int KT = DD / KSTG;             // 8
constexpr int STAGE_BYTES = 2 * 128 * 128;  // A tile + B tile = 32KB
constexpr int B_OFF = 128 * 128;            // 16KB

__device__ __forceinline__ void cp_async16(uint32_t s, const void* g) {
    asm volatile("cp.async.cg.shared.global [%0], [%1], 16;\n" :: "r"(s), "l"(g));
}
__device__ __forceinline__ void cp_commit() {
    asm volatile("cp.async.commit_group;\n");
}
template <int N>
__device__ __forceinline__ void cp_wait() {
    asm volatile("cp.async.wait_group %0;\n" :: "n"(N));
}
__device__ __forceinline__ void ldsm4(uint32_t& r0, uint32_t& r1, uint32_t& r2,
                                      uint32_t& r3, uint32_t addr) {
    asm volatile("ldmatrix.sync.aligned.m8n8.x4.shared.b16 {%0,%1,%2,%3}, [%4];\n"
                 : "=r"(r0), "=r"(r1), "=r"(r2), "=r"(r3) : "r"(addr));
}
__device__ __forceinline__ void mma16832_s8(int* c, const uint32_t* a,
                                            const uint32_t* b) {
    asm volatile(
        "mma.sync.aligned.m16n8k32.row.col.s32.s8.s8.s32 "
        "{%0,%1,%2,%3}, {%4,%5,%6,%7}, {%8,%9}, {%0,%1,%2,%3};\n"
        : "+r"(c[0]), "+r"(c[1]), "+r"(c[2]), "+r"(c[3])
        : "r"(a[0]), "r"(a[1]), "r"(a[2]), "r"(a[3]), "r"(b[0]), "r"(b[1]));
}

__global__ __launch_bounds__(256) void gemm_i8_exp_kernel() {
    extern __shared__ char smem[];
    const uint32_t sbase = (uint32_t)__cvta_generic_to_shared(smem);
    const int tid = threadIdx.x;
    const int wid = tid >> 5;
    const int lane = tid & 31;
    const int warp_m = wid & 1;   // 0..1, 64 rows each
    const int warp_n = wid >> 1;  // 0..3, 32 cols each
    const int bi = blockIdx.y * 128;
    const int bj = blockIdx.x * 128;

    int acc[4][4][4];
#pragma unroll
    for (int mt = 0; mt < 4; mt++)
#pragma unroll
        for (int nt = 0; nt < 4; nt++)
#pragma unroll
            for (int r = 0; r < 4; r++) acc[mt][nt][r] = 0;

    auto load_stage = [&](int kt, int stage) {
        const int k0 = kt * KSTG;
        const uint32_t so = sbase + stage * STAGE_BYTES;
#pragma unroll
        for (int i = 0; i < 4; i++) {
            int u = tid + i * 256;   // 1024 16B units per tile
            int row = u >> 3;
            int chunk = u & 7;
            uint32_t d = so + row * 128 + ((chunk * 16) ^ ((row & 7) << 4));
            cp_async16(d, &g_A8[(size_t)(bi + row) * DD + k0 + chunk * 16]);
            cp_async16(d + B_OFF, &g_B8[(size_t)(bj + row) * DD + k0 + chunk * 16]);
        }
        cp_commit();
    };

    load_stage(0, 0);

    for (int kt = 0; kt < KT; kt++) {
        const int stage = kt & 1;
        if (kt + 1 < KT) {
            load_stage(kt + 1, stage ^ 1);
            cp_wait<1>();
        } else {
            cp_wait<0>();
        }
        __syncthreads();

        const uint32_t sa = sbase + stage * STAGE_BYTES;
        const uint32_t sb = sa + B_OFF;
#pragma unroll
        for (int kk = 0; kk < 4; kk++) {   // each kk: K=32 int8 = 2 chunks
            uint32_t a[4][4];
#pragma unroll
            for (int mt = 0; mt < 4; mt++) {
                int row = warp_m * 64 + mt * 16 + (lane & 15);
                int chunk = kk * 2 + (lane >> 4);
                uint32_t addr = sa + row * 128 + ((chunk * 16) ^ ((row & 7) << 4));
                ldsm4(a[mt][0], a[mt][1], a[mt][2], a[mt][3], addr);
            }
            uint32_t b[2][4];
#pragma unroll
            for (int pair = 0; pair < 2; pair++) {
                int rown = warp_n * 32 + pair * 16 + ((lane >> 4) << 3) + (lane & 7);
                int chunk = kk * 2 + ((lane >> 3) & 1);
                uint32_t addr = sb + rown * 128 + ((chunk * 16) ^ ((rown & 7) << 4));
                ldsm4(b[pair][0], b[pair][1], b[pair][2], b[pair][3], addr);
            }
#pragma unroll
            for (int mt = 0; mt < 4; mt++)
#pragma unroll
                for (int nt = 0; nt < 4; nt++)
                    mma16832_s8(acc[mt][nt], a[mt], &b[nt >> 1][(nt & 1) * 2]);
        }
        __syncthreads();
    }

    // Epilogue stage 1: exp(acc/65536 - 1) -> e4m3 into smem tile (128x128)
    const int lrow = lane >> 2;
    const int lcol = (lane & 3) * 2;
#pragma unroll
    for (int mt = 0; mt < 4; mt++) {
#pragma unroll
        for (int nt = 0; nt < 4; nt++) {
            int r0 = warp_m * 64 + mt * 16 + lrow;
            int cc = warp_n * 32 + nt * 8 + lcol;
            unsigned short p0 = f32x2_to_e4m3x2(
                __expf(__int2float_rn(acc[mt][nt][0]) * ACCSCALE - 1.0f),
                __expf(__int2float_rn(acc[mt][nt][1]) * ACCSCALE - 1.0f));
            unsigned short p1 = f32x2_to_e4m3x2(
                __expf(__int2float_rn(acc[mt][nt][2]) * ACCSCALE - 1.0f),
                __expf(__int2float_rn(acc[mt][nt][3]) * ACCSCALE - 1.0f));
            *reinterpret_cast<unsigned short*>(smem + r0 * 128 + cc) = p0;
            *reinterpret_cast<unsigned short*>(smem + (r0 + 8) * 128 + cc) = p1;
        }
    }
    __syncthreads();

    // Epilogue stage 2: coalesced uint4 stores
    {
        const uint4* st = reinterpret_cast<const uint4*>(smem);
        int base = tid * 4;             // uint4 index
        int row = base >> 3;            // 8 uint4 per 128B row
        int coloff = (base & 7) * 16;   // byte offset in row
        uint4* gp = reinterpret_cast<uint4*>(
            &g_P0[(size_t)(bi + row) * NN + bj + coloff]);
#pragma unroll
        for (int q = 0; q < 4; q++) gp[q] = st[base + q];
    }
}

// ---------------- byte transpose: g_P0T = g_P0^T (tiled, 128x128) ----------
__global__ __launch_bounds__(256) void transpose_kernel() {
    __shared__ uint8_t t[128 * 132];   // padded stride -> conflict-free cols
    const int tid = threadIdx.x;
    const int bi = blockIdx.y * 128;   // P0 row block
    const int bj = blockIdx.x * 128;   // P0 col block
#pragma unroll
    for (int i = 0; i < 4; i++) {
        int u = tid + i * 256;
        int row = u >> 3, ch = u & 7;
        uint4 v = *reinterpret_cast<const uint4*>(
            &g_P0[(size_t)(bi + row) * NN + bj + ch * 16]);
        uint32_t* dst = reinterpret_cast<uint32_t*>(&t[row * 132 + ch * 16]);
        dst[0] = v.x; dst[1] = v.y; dst[2] = v.z; dst[3] = v.w;
    }
    __syncthreads();
#pragma unroll
    for (int i = 0; i < 4; i++) {
        int u = tid + i * 256;
        int tcol = u >> 3, rch = u & 7;   // P0T row-in-tile, 16-row chunk
        uint32_t wv[4];
#pragma unroll
        for (int q = 0; q < 4; q++) {
            uint32_t x = 0;
#pragma unroll
            for (int bb = 0; bb < 4; bb++) {
                int r = rch * 16 + q * 4 + bb;
                x |= (uint32_t)t[r * 132 + tcol] << (8 * bb);
            }
            wv[q] = x;
        }
        *reinterpret_cast<uint4*>(
            &g_P0T[(size_t)(bj + tcol) * NN + bi + rch * 16]) =
            make_uint4(wv[0], wv[1], wv[2], wv[3]);
    }
}

// ---------------- weighted column-sum stream (replaces dual matvec) --------
// z=0: out_b[j] += sum_i P0 [i][j] * f(b[i])   (== old out_col)
// z=1: out_a[j] += sum_i P0T[i][j] * f(a[i])   (== old out_row)
// f(x) = 1/x when RECIP else x; common-mode normalized by element 0.
// Pure stream: uint2 loads, 8 cols/thread, NO shfl / row reduction.
template <bool RECIP>
__global__ __launch_bounds__(256) void colsum_kernel(
    const float* __restrict__ a, const float* __restrict__ b,
    float* __restrict__ out_a, float* __restrict__ out_b) {
    const int ROWS = 64;
    const int tid = threadIdx.x;
    const bool zt = (blockIdx.z == 1);
    const uint8_t* M = zt ? g_P0T : g_P0;
    const float* w = zt ? a : b;
    float* out = zt ? out_a : out_b;
    const int j = (blockIdx.x * 256 + tid) * 8;
    const int i0 = blockIdx.y * ROWS;
    __shared__ __half2 wsh[ROWS];
    const float w0 = w[0];
    if (tid < ROWS) {
        float v = w[i0 + tid];
        wsh[tid] = __float2half2_rn(RECIP ? (w0 / v) : (v / w0));
    }
    __syncthreads();

    const uint8_t* base = M + (size_t)i0 * NN + j;
    float acc[8];
#pragma unroll
    for (int k = 0; k < 8; k++) acc[k] = 0.0f;
    const __half2 zero2 = __floats2half2_rn(0.f, 0.f);

#pragma unroll
    for (int ch = 0; ch < 2; ch++) {    // 2 x 32-row half2 chunks (precision)
        __half2 c01 = zero2, c23 = zero2, c45 = zero2, c67 = zero2;
#pragma unroll 8
        for (int r = 0; r < 32; r++) {
            const int ii = ch * 32 + r;
            uint2 u = ldg_u64_nc(base + (size_t)ii * NN);
            __half2 va = e4m3x2_to_h2((unsigned short)(u.x & 0xffffu));
            __half2 vb = e4m3x2_to_h2((unsigned short)(u.x >> 16));
            __half2 vc = e4m3x2_to_h2((unsigned short)(u.y & 0xffffu));
            __half2 vd = e4m3x2_to_h2((unsigned short)(u.y >> 16));
            __half2 ww = wsh[ii];
            c01 = __hfma2(va, ww, c01);
            c23 = __hfma2(vb, ww, c23);
            c45 = __hfma2(vc, ww, c45);
            c67 = __hfma2(vd, ww, c67);
        }
        acc[0] += __low2float(c01); acc[1] += __high2float(c01);
        acc[2] += __low2float(c23); acc[3] += __high2float(c23);
        acc[4] += __low2float(c45); acc[5] += __high2float(c45);
        acc[6] += __low2float(c67); acc[7] += __high2float(c67);
    }
    const float s = RECIP ? (1.0f / w0) : w0;
#pragma unroll
    for (int k = 0; k < 8; k++) atomicAdd(&out[j + k], acc[k] * s);
}

// colupd: r = 1/u (persists for CE), c/c2 two-step update from s/s2,
// then zero u,u2,s,s2 for next iteration / CE accumulators.
__global__ void colupd_kernel() {
    int i = blockIdx.x * blockDim.x + threadIdx.x;
    if (i < NN) {
        g_r[i] = 1.0f / g_u[i];
        g_r2[i] = 1.0f / g_u2[i];
        float cv = g_c[i], sv = g_s[i];
        cv *= fmaxf(BD / (cv * sv), 1.0f);
        cv *= fminf(BU / (cv * sv), 1.0f);
        g_c[i] = cv;
        float cv2 = g_c2[i], sv2 = g_s2[i];
        cv2 *= fmaxf(BD / (cv2 * sv2), 1.0f);
        cv2 *= fminf(BU / (cv2 * sv2), 1.0f);
        g_c2[i] = cv2;
        g_u[i] = 0.0f; g_u2[i] = 0.0f;
        g_s[i] = 0.0f; g_s2[i] = 0.0f;
    }
}

// ---------------- diag terms ----------------
__global__ __launch_bounds__(256) void diag_kernel(const int* __restrict__ labels) {
    int i = blockIdx.x * 256 + threadIdx.x;
    int lab = labels[i];
    float v1 = e4m3_byte_to_f32(g_P0[(size_t)i * NN + lab]);
    g_diag[i] = g_r[i] * v1 * g_c[lab];
    float v2 = e4m3_byte_to_f32(g_P0[(size_t)lab * NN + i]);
    g_diag2[i] = g_r2[i] * v2 * g_c2[lab];
}

// ---------------- fused CE: both logsumexps in ONE read of P0, half2 exp ----
__global__ __launch_bounds__(256) void ce_fused_kernel() {
    const int ROWS = 64;
    const int tid = threadIdx.x;
    const int j = (blockIdx.x * 256 + tid) * 4;
    const int i0 = blockIdx.y * ROWS;
    __shared__ __half2 Fsh[ROWS];   // r_i * c0 (broadcast pair)
    __shared__ __half2 Csh[ROWS];   // c2_i / c2_0 (broadcast pair)
    __shared__ float rowpart[ROWS][9];
    const float c0 = g_c[0];
    const float c20 = g_c2[0];
    if (tid < ROWS) {
        Fsh[tid] = __float2half2_rn(g_r[i0 + tid] * c0);
        Csh[tid] = __float2half2_rn(g_c2[i0 + tid] / c20);
    }
    __syncthreads();

    __half2 cn01, cn23, G01, G23;
    {
        float4 cv = *reinterpret_cast<const float4*>(&g_c[j]);
        float4 rv = *reinterpret_cast<const float4*>(&g_r2[j]);
        cn01 = __floats2half2_rn(cv.x / c0, cv.y / c0);
        cn23 = __floats2half2_rn(cv.z / c0, cv.w / c0);
        G01 = __floats2half2_rn(rv.x * c20, rv.y * c20);
        G23 = __floats2half2_rn(rv.z * c20, rv.w * c20);
    }
    const __half2 zero2 = __floats2half2_rn(0.f, 0.f);
    __half2 colacc01 = zero2, colacc23 = zero2;
    const int warp = tid >> 5, lane = tid & 31;
    const uint8_t* base = g_P0 + (size_t)i0 * NN + j;

    for (int ii = 0; ii < ROWS; ii += 2) {
        uint32_t u0 = ldg_u32_nc(base + (size_t)ii * NN);
        uint32_t u1 = ldg_u32_nc(base + (size_t)(ii + 1) * NN);
        __half2 v0a = e4m3x2_to_h2((unsigned short)(u0 & 0xffffu));
        __half2 v0b = e4m3x2_to_h2((unsigned short)(u0 >> 16));
        __half2 v1a = e4m3x2_to_h2((unsigned short)(u1 & 0xffffu));
        __half2 v1b = e4m3x2_to_h2((unsigned short)(u1 >> 16));
        __half2 F0 = Fsh[ii], F1 = Fsh[ii + 1];
        __half2 C0 = Csh[ii], C1 = Csh[ii + 1];
        __half2 x0 = __hadd2(h2exp(__hmul2(__hmul2(F0, cn01), v0a)),
                             h2exp(__hmul2(__hmul2(F0, cn23), v0b)));
        __half2 x1 = __hadd2(h2exp(__hmul2(__hmul2(F1, cn01), v1a)),
                             h2exp(__hmul2(__hmul2(F1, cn23), v1b)));
        colacc01 = __hadd2(colacc01, h2exp(__hmul2(__hmul2(G01, C0), v0a)));
        colacc23 = __hadd2(colacc23, h2exp(__hmul2(__hmul2(G23, C0), v0b)));
        colacc01 = __hadd2(colacc01, h2exp(__hmul2(__hmul2(G01, C1), v1a)));
        colacc23 = __hadd2(colacc23, h2exp(__hmul2(__hmul2(G23, C1), v1b)));
        __half2 lo = __halves2half2(__low2half(x0), __low2half(x1));
        __half2 hi = __halves2half2(__high2half(x0), __high2half(x1));
        __half2 dd = __hadd2(lo, hi);
#pragma unroll
        for (int o = 16; o > 0; o >>= 1)
            dd = __hadd2(dd, shfl_down_h2(dd, o));
        if (lane == 0) {
            rowpart[ii][warp] = __low2float(dd);
            rowpart[ii + 1][warp] = __high2float(dd);
        }
    }
    __syncthreads();
    if (tid < ROWS) {
        float sacc = 0.f;
#pragma unroll
        for (int w = 0; w < 8; w++) sacc += rowpart[tid][w];
        atomicAdd(&g_u[i0 + tid], sacc);
    }
    atomicAdd(&g_u2[j + 0], __low2float(colacc01));
    atomicAdd(&g_u2[j + 1], __high2float(colacc01));
    atomicAdd(&g_u2[j + 2], __low2float(colacc23));
    atomicAdd(&g_u2[j + 3], __high2float(colacc23));
}

__global__ __launch_bounds__(256) void ce_reduce_kernel() {
    int t = blockIdx.x * 256 + threadIdx.x;
    float v = (logf(g_u[t]) - g_diag[t]) + (logf(g_u2[t]) - g_diag2[t]);
    __shared__ float wsum[8];
#pragma unroll
    for (int o = 16; o > 0; o >>= 1)
        v += __shfl_down_sync(0xffffffffu, v, o);
    int warp = threadIdx.x >> 5, lane = threadIdx.x & 31;
    if (lane == 0) wsum[warp] = v;
    __syncthreads();
    if (threadIdx.x == 0) {
        float tt = 0.f;
#pragma unroll
        for (int w = 0; w < 8; w++) tt += wsum[w];
        atomicAdd(&g_sums[0], tt);
    }
}

__global__ void finalize_kernel(float* __restrict__ out) {
    out[0] = g_sums[0] / (2.0f * (float)NN);
}

// ---------------- launch ----------------
extern "C" void kernel_launch(void* const* d_in, const int* in_sizes, int n_in,
                              void* d_out, int out_size) {
    const float* A = (const float*)d_in[0];   // all_image_features [N, D]
    const float* B = (const float*)d_in[1];   // all_text_features  [N, D]
    const int* labels = (const int*)d_in[3];
    float* out = (float*)d_out;

    float *c, *c2, *u, *u2, *s, *s2;
    cudaGetSymbolAddress((void**)&c, g_c);
    cudaGetSymbolAddress((void**)&c2, g_c2);
    cudaGetSymbolAddress((void**)&u, g_u);
    cudaGetSymbolAddress((void**)&u2, g_u2);
    cudaGetSymbolAddress((void**)&s, g_s);
    cudaGetSymbolAddress((void**)&s2, g_s2);

    cudaFuncSetAttribute(gemm_i8_exp_kernel,
                         cudaFuncAttributeMaxDynamicSharedMemorySize,
                         2 * STAGE_BYTES);

    init_kernel<<<NN / 256, 256>>>();
    convert_kernel<<<NN * DD / 4 / 256, 256>>>(A, B);
    gemm_i8_exp_kernel<<<dim3(64, 64), 256, 2 * STAGE_BYTES>>>();
    transpose_kernel<<<dim3(64, 64), 256>>>();

    for (int it = 0; it < 5; it++) {
        // pass1: u = rowsum(P0; c) via P0T-colsum ; u2 = colsum(P0; c2)
        colsum_kernel<false><<<dim3(4, 128, 2), 256>>>(c, c2, u, u2);
        // pass2: s2 = rowsum(P0; 1/u2) via P0T-colsum ; s = colsum(P0; 1/u)
        colsum_kernel<true><<<dim3(4, 128, 2), 256>>>(u2, u, s2, s);
        colupd_kernel<<<NN / 256, 256>>>();
    }

    diag_kernel<<<NN / 256, 256>>>(labels);
    ce_fused_kernel<<<dim3(8, 128), 256>>>();
    ce_reduce_kernel<<<NN / 256, 256>>>();
    finalize_kernel<<<1, 1>>>(out);
}

// round 14
// speedup vs baseline: 1.6378x; 1.6378x over previous
#include <cuda_runtime.h>
#include <cuda_bf16.h>
#include <cuda_fp16.h>
#include <math.h>
#include <stdint.h>

// Problem constants
constexpr int NN = 8192;
constexpr int DD = 1024;
constexpr float BD = 819.2f;   // 0.1 * n
constexpr float BU = 7372.8f;  // 0.9 * n
constexpr float INSCALE = 256.0f;            // int8 quantization scale
constexpr float ACCSCALE = 1.0f / 65536.0f;  // 1/(256*256)

// ---------------- device scratch (static, allocation-free) ----------------
__device__ uint8_t g_P0[(size_t)NN * NN];   // 64 MB, e4m3 of exp(L - 1)
__device__ int8_t g_A8[(size_t)NN * DD];    // 8 MB, int8 of 256*A
__device__ int8_t g_B8[(size_t)NN * DD];    // 8 MB, int8 of 256*B
__device__ float g_c[NN], g_c2[NN];
__device__ float g_r[NN], g_r2[NN];
__device__ float g_u[NN], g_u2[NN];   // row sums; reused as CE S accumulators
__device__ float g_s[NN], g_s2[NN];   // col sums
__device__ float g_diag[NN], g_diag2[NN];
__device__ float g_sums[1];

// ---------------- fp8 helpers ----------------
__device__ __forceinline__ unsigned short f32x2_to_e4m3x2(float lo, float hi) {
    unsigned short r;
    asm("cvt.rn.satfinite.e4m3x2.f32 %0, %1, %2;" : "=h"(r) : "f"(hi), "f"(lo));
    return r;
}
__device__ __forceinline__ __half2 e4m3x2_to_h2(unsigned short s) {
    uint32_t h;
    asm("cvt.rn.f16x2.e4m3x2 %0, %1;" : "=r"(h) : "h"(s));
    return *reinterpret_cast<__half2*>(&h);
}
__device__ __forceinline__ float e4m3_byte_to_f32(uint8_t b) {
    return __low2float(e4m3x2_to_h2((unsigned short)b));
}
__device__ __forceinline__ __half2 shfl_down_h2(__half2 v, int o) {
    uint32_t u = *reinterpret_cast<uint32_t*>(&v);
    u = __shfl_down_sync(0xffffffffu, u, o);
    return *reinterpret_cast<__half2*>(&u);
}
__device__ __forceinline__ uint32_t ldg_u32_nc(const uint8_t* p) {
    uint32_t u;
    asm volatile("ld.global.nc.u32 %0, [%1];" : "=r"(u) : "l"(p));
    return u;
}

// ---------------- init ----------------
__global__ void init_kernel() {
    int i = blockIdx.x * blockDim.x + threadIdx.x;
    if (i < NN) {
        g_c[i] = 1.0f; g_c2[i] = 1.0f;
        g_u[i] = 0.0f; g_u2[i] = 0.0f;
        g_s[i] = 0.0f; g_s2[i] = 0.0f;
    }
    if (i == 0) g_sums[0] = 0.0f;
}

// ---------------- fp32 -> int8 convert (scale 256) ----------------
__device__ __forceinline__ uint32_t quant4(float4 v) {
    int i0 = __float2int_rn(fminf(fmaxf(v.x * INSCALE, -127.f), 127.f));
    int i1 = __float2int_rn(fminf(fmaxf(v.y * INSCALE, -127.f), 127.f));
    int i2 = __float2int_rn(fminf(fmaxf(v.z * INSCALE, -127.f), 127.f));
    int i3 = __float2int_rn(fminf(fmaxf(v.w * INSCALE, -127.f), 127.f));
    return (uint32_t)(i0 & 255) | ((uint32_t)(i1 & 255) << 8) |
           ((uint32_t)(i2 & 255) << 16) | ((uint32_t)(i3 & 255) << 24);
}
__global__ __launch_bounds__(256) void convert_kernel(
    const float* __restrict__ A, const float* __restrict__ B) {
    int i = blockIdx.x * blockDim.x + threadIdx.x;  // float4 index
    const int n4 = NN * DD / 4;
    if (i < n4) {
        reinterpret_cast<uint32_t*>(g_A8)[i] =
            quant4(reinterpret_cast<const float4*>(A)[i]);
        reinterpret_cast<uint32_t*>(g_B8)[i] =
            quant4(reinterpret_cast<const float4*>(B)[i]);
    }
}

// ---------------- int8 tensor-core GEMM: P0 = e4m3(exp(acc/65536 - 1)) ------
constexpr int KSTG = 128;                 // K elements (bytes) per stage
constexpr int KT = DD / KSTG;             // 8
constexpr int STAGE_BYTES = 2 * 128 * 128;  // A tile + B tile = 32KB
constexpr int B_OFF = 128 * 128;            // 16KB

__device__ __forceinline__ void cp_async16(uint32_t s, const void* g) {
    asm volatile("cp.async.cg.shared.global [%0], [%1], 16;\n" :: "r"(s), "l"(g));
}
__device__ __forceinline__ void cp_commit() {
    asm volatile("cp.async.commit_group;\n");
}
template <int N>
__device__ __forceinline__ void cp_wait() {
    asm volatile("cp.async.wait_group %0;\n" :: "n"(N));
}
__device__ __forceinline__ void ldsm4(uint32_t& r0, uint32_t& r1, uint32_t& r2,
                                      uint32_t& r3, uint32_t addr) {
    asm volatile("ldmatrix.sync.aligned.m8n8.x4.shared.b16 {%0,%1,%2,%3}, [%4];\n"
                 : "=r"(r0), "=r"(r1), "=r"(r2), "=r"(r3) : "r"(addr));
}
__device__ __forceinline__ void mma16832_s8(int* c, const uint32_t* a,
                                            const uint32_t* b) {
    asm volatile(
        "mma.sync.aligned.m16n8k32.row.col.s32.s8.s8.s32 "
        "{%0,%1,%2,%3}, {%4,%5,%6,%7}, {%8,%9}, {%0,%1,%2,%3};\n"
        : "+r"(c[0]), "+r"(c[1]), "+r"(c[2]), "+r"(c[3])
        : "r"(a[0]), "r"(a[1]), "r"(a[2]), "r"(a[3]), "r"(b[0]), "r"(b[1]));
}

__global__ __launch_bounds__(256) void gemm_i8_exp_kernel() {
    extern __shared__ char smem[];
    const uint32_t sbase = (uint32_t)__cvta_generic_to_shared(smem);
    const int tid = threadIdx.x;
    const int wid = tid >> 5;
    const int lane = tid & 31;
    const int warp_m = wid & 1;   // 0..1, 64 rows each
    const int warp_n = wid >> 1;  // 0..3, 32 cols each
    const int bi = blockIdx.y * 128;
    const int bj = blockIdx.x * 128;

    int acc[4][4][4];
#pragma unroll
    for (int mt = 0; mt < 4; mt++)
#pragma unroll
        for (int nt = 0; nt < 4; nt++)
#pragma unroll
            for (int r = 0; r < 4; r++) acc[mt][nt][r] = 0;

    auto load_stage = [&](int kt, int stage) {
        const int k0 = kt * KSTG;
        const uint32_t so = sbase + stage * STAGE_BYTES;
#pragma unroll
        for (int i = 0; i < 4; i++) {
            int u = tid + i * 256;   // 1024 16B units per tile
            int row = u >> 3;
            int chunk = u & 7;
            uint32_t d = so + row * 128 + ((chunk * 16) ^ ((row & 7) << 4));
            cp_async16(d, &g_A8[(size_t)(bi + row) * DD + k0 + chunk * 16]);
            cp_async16(d + B_OFF, &g_B8[(size_t)(bj + row) * DD + k0 + chunk * 16]);
        }
        cp_commit();
    };

    load_stage(0, 0);

    for (int kt = 0; kt < KT; kt++) {
        const int stage = kt & 1;
        if (kt + 1 < KT) {
            load_stage(kt + 1, stage ^ 1);
            cp_wait<1>();
        } else {
            cp_wait<0>();
        }
        __syncthreads();

        const uint32_t sa = sbase + stage * STAGE_BYTES;
        const uint32_t sb = sa + B_OFF;
#pragma unroll
        for (int kk = 0; kk < 4; kk++) {   // each kk: K=32 int8 = 2 chunks
            uint32_t a[4][4];
#pragma unroll
            for (int mt = 0; mt < 4; mt++) {
                int row = warp_m * 64 + mt * 16 + (lane & 15);
                int chunk = kk * 2 + (lane >> 4);
                uint32_t addr = sa + row * 128 + ((chunk * 16) ^ ((row & 7) << 4));
                ldsm4(a[mt][0], a[mt][1], a[mt][2], a[mt][3], addr);
            }
            uint32_t b[2][4];
#pragma unroll
            for (int pair = 0; pair < 2; pair++) {
                int rown = warp_n * 32 + pair * 16 + ((lane >> 4) << 3) + (lane & 7);
                int chunk = kk * 2 + ((lane >> 3) & 1);
                uint32_t addr = sb + rown * 128 + ((chunk * 16) ^ ((rown & 7) << 4));
                ldsm4(b[pair][0], b[pair][1], b[pair][2], b[pair][3], addr);
            }
#pragma unroll
            for (int mt = 0; mt < 4; mt++)
#pragma unroll
                for (int nt = 0; nt < 4; nt++)
                    mma16832_s8(acc[mt][nt], a[mt], &b[nt >> 1][(nt & 1) * 2]);
        }
        __syncthreads();
    }

    // Epilogue stage 1: exp(acc/65536 - 1) -> e4m3 into smem tile (128x128)
    const int lrow = lane >> 2;
    const int lcol = (lane & 3) * 2;
#pragma unroll
    for (int mt = 0; mt < 4; mt++) {
#pragma unroll
        for (int nt = 0; nt < 4; nt++) {
            int r0 = warp_m * 64 + mt * 16 + lrow;
            int cc = warp_n * 32 + nt * 8 + lcol;
            unsigned short p0 = f32x2_to_e4m3x2(
                __expf(__int2float_rn(acc[mt][nt][0]) * ACCSCALE - 1.0f),
                __expf(__int2float_rn(acc[mt][nt][1]) * ACCSCALE - 1.0f));
            unsigned short p1 = f32x2_to_e4m3x2(
                __expf(__int2float_rn(acc[mt][nt][2]) * ACCSCALE - 1.0f),
                __expf(__int2float_rn(acc[mt][nt][3]) * ACCSCALE - 1.0f));
            *reinterpret_cast<unsigned short*>(smem + r0 * 128 + cc) = p0;
            *reinterpret_cast<unsigned short*>(smem + (r0 + 8) * 128 + cc) = p1;
        }
    }
    __syncthreads();

    // Epilogue stage 2: coalesced uint4 stores
    {
        const uint4* st = reinterpret_cast<const uint4*>(smem);
        int base = tid * 4;             // uint4 index
        int row = base >> 3;            // 8 uint4 per 128B row
        int coloff = (base & 7) * 16;   // byte offset in row
        uint4* gp = reinterpret_cast<uint4*>(
            &g_P0[(size_t)(bi + row) * NN + bj + coloff]);
#pragma unroll
        for (int q = 0; q < 4; q++) gp[q] = st[base + q];
    }
}

// ---------------- fused dual matvec: proven shape + half2 + load prefetch ---
// out_row[i] += sum_j P0[i][j]*f(a[j]); out_col[j] += sum_i P0[i][j]*f(b[i])
// f(x)=1/x if RECIP. Shape: ROWS=64, 4 cols/thread, grid (8,128).
// Software pipeline: next row-pair's loads issue before current pair's
// compute + shfl tree (raises per-thread MLP 2 -> 4).
template <bool RECIP>
__global__ __launch_bounds__(256) void dual_matvec_kernel(
    const float* __restrict__ a, const float* __restrict__ b,
    float* __restrict__ out_row, float* __restrict__ out_col) {
    const int ROWS = 64;
    const int tid = threadIdx.x;
    const int j = (blockIdx.x * 256 + tid) * 4;
    const int i0 = blockIdx.y * ROWS;
    __shared__ __half2 bsh[ROWS];
    __shared__ float rowpart[ROWS][9];
    const float a0 = a[0];
    const float b0 = b[0];
    if (tid < ROWS) {
        float v = b[i0 + tid];
        float w = RECIP ? (b0 / v) : (v / b0);
        bsh[tid] = __float2half2_rn(w);
    }
    __syncthreads();

    __half2 ah01, ah23;
    {
        float4 t = *reinterpret_cast<const float4*>(&a[j]);
        float x0 = RECIP ? (a0 / t.x) : (t.x / a0);
        float x1 = RECIP ? (a0 / t.y) : (t.y / a0);
        float x2 = RECIP ? (a0 / t.z) : (t.z / a0);
        float x3 = RECIP ? (a0 / t.w) : (t.w / a0);
        ah01 = __floats2half2_rn(x0, x1);
        ah23 = __floats2half2_rn(x2, x3);
    }
    float c0 = 0.f, c1 = 0.f, c2 = 0.f, c3 = 0.f;   // f32 column totals
    const int warp = tid >> 5, lane = tid & 31;
    const uint8_t* base = g_P0 + (size_t)i0 * NN + j;

    const __half2 zero2 = __floats2half2_rn(0.f, 0.f);
    // prefetch first row pair
    uint32_t pu0 = ldg_u32_nc(base);
    uint32_t pu1 = ldg_u32_nc(base + NN);
#pragma unroll
    for (int chunk = 0; chunk < 2; chunk++) {       // 2 x 32-row chunks
        __half2 cacc01 = zero2, cacc23 = zero2;
#pragma unroll 4
        for (int it2 = 0; it2 < 16; it2++) {
            const int ii = chunk * 32 + it2 * 2;
            const uint32_t u0 = pu0;
            const uint32_t u1 = pu1;
            if (ii + 2 < ROWS) {   // prefetch next pair before compute
                pu0 = ldg_u32_nc(base + (size_t)(ii + 2) * NN);
                pu1 = ldg_u32_nc(base + (size_t)(ii + 3) * NN);
            }
            __half2 v0a = e4m3x2_to_h2((unsigned short)(u0 & 0xffffu));
            __half2 v0b = e4m3x2_to_h2((unsigned short)(u0 >> 16));
            __half2 v1a = e4m3x2_to_h2((unsigned short)(u1 & 0xffffu));
            __half2 v1b = e4m3x2_to_h2((unsigned short)(u1 >> 16));
            __half2 bb0 = bsh[ii], bb1 = bsh[ii + 1];
            cacc01 = __hfma2(v0a, bb0, cacc01);
            cacc23 = __hfma2(v0b, bb0, cacc23);
            cacc01 = __hfma2(v1a, bb1, cacc01);
            cacc23 = __hfma2(v1b, bb1, cacc23);
            __half2 d0 = __hfma2(v0b, ah23, __hmul2(v0a, ah01));
            __half2 d1 = __hfma2(v1b, ah23, __hmul2(v1a, ah01));
            __half2 lo = __halves2half2(__low2half(d0), __low2half(d1));
            __half2 hi = __halves2half2(__high2half(d0), __high2half(d1));
            __half2 dd = __hadd2(lo, hi);
#pragma unroll
            for (int o = 16; o > 0; o >>= 1)
                dd = __hadd2(dd, shfl_down_h2(dd, o));
            if (lane == 0) {
                rowpart[ii][warp] = __low2float(dd);
                rowpart[ii + 1][warp] = __high2float(dd);
            }
        }
        c0 += __low2float(cacc01); c1 += __high2float(cacc01);
        c2 += __low2float(cacc23); c3 += __high2float(cacc23);
    }
    __syncthreads();
    const float s_a = RECIP ? (1.0f / a0) : a0;
    const float s_b = RECIP ? (1.0f / b0) : b0;
    if (tid < ROWS) {
        float sacc = 0.f;
#pragma unroll
        for (int w = 0; w < 8; w++) sacc += rowpart[tid][w];
        atomicAdd(&out_row[i0 + tid], sacc * s_a);
    }
    atomicAdd(&out_col[j + 0], c0 * s_b);
    atomicAdd(&out_col[j + 1], c1 * s_b);
    atomicAdd(&out_col[j + 2], c2 * s_b);
    atomicAdd(&out_col[j + 3], c3 * s_b);
}

// colupd: r = 1/u (persists for CE), c/c2 two-step update from s/s2,
// then zero u,u2,s,s2 for next iteration / CE accumulators.
__global__ void colupd_kernel() {
    int i = blockIdx.x * blockDim.x + threadIdx.x;
    if (i < NN) {
        g_r[i] = 1.0f / g_u[i];
        g_r2[i] = 1.0f / g_u2[i];
        float cv = g_c[i], sv = g_s[i];
        cv *= fmaxf(BD / (cv * sv), 1.0f);
        cv *= fminf(BU / (cv * sv), 1.0f);
        g_c[i] = cv;
        float cv2 = g_c2[i], sv2 = g_s2[i];
        cv2 *= fmaxf(BD / (cv2 * sv2), 1.0f);
        cv2 *= fminf(BU / (cv2 * sv2), 1.0f);
        g_c2[i] = cv2;
        g_u[i] = 0.0f; g_u2[i] = 0.0f;
        g_s[i] = 0.0f; g_s2[i] = 0.0f;
    }
}

// ---------------- diag terms ----------------
__global__ __launch_bounds__(256) void diag_kernel(const int* __restrict__ labels) {
    int i = blockIdx.x * 256 + threadIdx.x;
    int lab = labels[i];
    float v1 = e4m3_byte_to_f32(g_P0[(size_t)i * NN + lab]);
    g_diag[i] = g_r[i] * v1 * g_c[lab];
    float v2 = e4m3_byte_to_f32(g_P0[(size_t)lab * NN + i]);
    g_diag2[i] = g_r2[i] * v2 * g_c2[lab];
}

// ---------------- fused CE: both logsumexps in ONE read of P0, half2 exp ----
__global__ __launch_bounds__(256) void ce_fused_kernel() {
    const int ROWS = 64;
    const int tid = threadIdx.x;
    const int j = (blockIdx.x * 256 + tid) * 4;
    const int i0 = blockIdx.y * ROWS;
    __shared__ __half2 Fsh[ROWS];   // r_i * c0
    __shared__ __half2 Csh[ROWS];   // c2_i / c2_0
    __shared__ float rowpart[ROWS][9];
    const float c0 = g_c[0];
    const float c20 = g_c2[0];
    if (tid < ROWS) {
        Fsh[tid] = __float2half2_rn(g_r[i0 + tid] * c0);
        Csh[tid] = __float2half2_rn(g_c2[i0 + tid] / c20);
    }
    __syncthreads();

    __half2 cn01, cn23, G01, G23;
    {
        float4 cv = *reinterpret_cast<const float4*>(&g_c[j]);
        float4 rv = *reinterpret_cast<const float4*>(&g_r2[j]);
        cn01 = __floats2half2_rn(cv.x / c0, cv.y / c0);
        cn23 = __floats2half2_rn(cv.z / c0, cv.w / c0);
        G01 = __floats2half2_rn(rv.x * c20, rv.y * c20);
        G23 = __floats2half2_rn(rv.z * c20, rv.w * c20);
    }
    const __half2 zero2 = __floats2half2_rn(0.f, 0.f);
    __half2 colacc01 = zero2, colacc23 = zero2;
    const int warp = tid >> 5, lane = tid & 31;
    const uint8_t* base = g_P0 + (size_t)i0 * NN + j;

    uint32_t pu0 = ldg_u32_nc(base);
    uint32_t pu1 = ldg_u32_nc(base + NN);
    for (int ii = 0; ii < ROWS; ii += 2) {
        const uint32_t u0 = pu0;
        const uint32_t u1 = pu1;
        if (ii + 2 < ROWS) {
            pu0 = ldg_u32_nc(base + (size_t)(ii + 2) * NN);
            pu1 = ldg_u32_nc(base + (size_t)(ii + 3) * NN);
        }
        __half2 v0a = e4m3x2_to_h2((unsigned short)(u0 & 0xffffu));
        __half2 v0b = e4m3x2_to_h2((unsigned short)(u0 >> 16));
        __half2 v1a = e4m3x2_to_h2((unsigned short)(u1 & 0xffffu));
        __half2 v1b = e4m3x2_to_h2((unsigned short)(u1 >> 16));
        __half2 F0 = Fsh[ii], F1 = Fsh[ii + 1];
        __half2 C0 = Csh[ii], C1 = Csh[ii + 1];
        __half2 x0 = __hadd2(h2exp(__hmul2(__hmul2(F0, cn01), v0a)),
                             h2exp(__hmul2(__hmul2(F0, cn23), v0b)));
        __half2 x1 = __hadd2(h2exp(__hmul2(__hmul2(F1, cn01), v1a)),
                             h2exp(__hmul2(__hmul2(F1, cn23), v1b)));
        colacc01 = __hadd2(colacc01, h2exp(__hmul2(__hmul2(G01, C0), v0a)));
        colacc23 = __hadd2(colacc23, h2exp(__hmul2(__hmul2(G23, C0), v0b)));
        colacc01 = __hadd2(colacc01, h2exp(__hmul2(__hmul2(G01, C1), v1a)));
        colacc23 = __hadd2(colacc23, h2exp(__hmul2(__hmul2(G23, C1), v1b)));
        __half2 lo = __halves2half2(__low2half(x0), __low2half(x1));
        __half2 hi = __halves2half2(__high2half(x0), __high2half(x1));
        __half2 dd = __hadd2(lo, hi);
#pragma unroll
        for (int o = 16; o > 0; o >>= 1)
            dd = __hadd2(dd, shfl_down_h2(dd, o));
        if (lane == 0) {
            rowpart[ii][warp] = __low2float(dd);
            rowpart[ii + 1][warp] = __high2float(dd);
        }
    }
    __syncthreads();
    if (tid < ROWS) {
        float sacc = 0.f;
#pragma unroll
        for (int w = 0; w < 8; w++) sacc += rowpart[tid][w];
        atomicAdd(&g_u[i0 + tid], sacc);
    }
    atomicAdd(&g_u2[j + 0], __low2float(colacc01));
    atomicAdd(&g_u2[j + 1], __high2float(colacc01));
    atomicAdd(&g_u2[j + 2], __low2float(colacc23));
    atomicAdd(&g_u2[j + 3], __high2float(colacc23));
}

__global__ __launch_bounds__(256) void ce_reduce_kernel() {
    int t = blockIdx.x * 256 + threadIdx.x;
    float v = (logf(g_u[t]) - g_diag[t]) + (logf(g_u2[t]) - g_diag2[t]);
    __shared__ float wsum[8];
#pragma unroll
    for (int o = 16; o > 0; o >>= 1)
        v += __shfl_down_sync(0xffffffffu, v, o);
    int warp = threadIdx.x >> 5, lane = threadIdx.x & 31;
    if (lane == 0) wsum[warp] = v;
    __syncthreads();
    if (threadIdx.x == 0) {
        float tt = 0.f;
#pragma unroll
        for (int w = 0; w < 8; w++) tt += wsum[w];
        atomicAdd(&g_sums[0], tt);
    }
}

__global__ void finalize_kernel(float* __restrict__ out) {
    out[0] = g_sums[0] / (2.0f * (float)NN);
}

// ---------------- launch ----------------
extern "C" void kernel_launch(void* const* d_in, const int* in_sizes, int n_in,
                              void* d_out, int out_size) {
    const float* A = (const float*)d_in[0];   // all_image_features [N, D]
    const float* B = (const float*)d_in[1];   // all_text_features  [N, D]
    const int* labels = (const int*)d_in[3];
    float* out = (float*)d_out;

    float *c, *c2, *u, *u2, *s, *s2;
    cudaGetSymbolAddress((void**)&c, g_c);
    cudaGetSymbolAddress((void**)&c2, g_c2);
    cudaGetSymbolAddress((void**)&u, g_u);
    cudaGetSymbolAddress((void**)&u2, g_u2);
    cudaGetSymbolAddress((void**)&s, g_s);
    cudaGetSymbolAddress((void**)&s2, g_s2);

    cudaFuncSetAttribute(gemm_i8_exp_kernel,
                         cudaFuncAttributeMaxDynamicSharedMemorySize,
                         2 * STAGE_BYTES);

    init_kernel<<<NN / 256, 256>>>();
    convert_kernel<<<NN * DD / 4 / 256, 256>>>(A, B);
    gemm_i8_exp_kernel<<<dim3(64, 64), 256, 2 * STAGE_BYTES>>>();

    for (int it = 0; it < 5; it++) {
        // pass1: u_i += sum_j P0_ij c_j ; u2_j += sum_i P0_ij c2_i
        dual_matvec_kernel<false><<<dim3(8, 128), 256>>>(c, c2, u, u2);
        // pass2: s2_i += sum_j P0_ij (1/u2_j) ; s_j += sum_i P0_ij (1/u_i)
        dual_matvec_kernel<true><<<dim3(8, 128), 256>>>(u2, u, s2, s);
        colupd_kernel<<<NN / 256, 256>>>();
    }

    diag_kernel<<<NN / 256, 256>>>(labels);
    ce_fused_kernel<<<dim3(8, 128), 256>>>();
    ce_reduce_kernel<<<NN / 256, 256>>>();
    finalize_kernel<<<1, 1>>>(out);
}

// round 15
// speedup vs baseline: 1.6501x; 1.0075x over previous
#include <cuda_runtime.h>
#include <cuda_bf16.h>
#include <cuda_fp16.h>
#include <math.h>
#include <stdint.h>

// Problem constants
constexpr int NN = 8192;
constexpr int DD = 1024;
constexpr float BD = 819.2f;   // 0.1 * n
constexpr float BU = 7372.8f;  // 0.9 * n
constexpr float INSCALE = 256.0f;            // int8 quantization scale
constexpr float ACCSCALE = 1.0f / 65536.0f;  // 1/(256*256)

// ---------------- device scratch (static, allocation-free) ----------------
__device__ uint8_t g_P0[(size_t)NN * NN];   // 64 MB, e4m3 of exp(L - 1)
__device__ int8_t g_A8[(size_t)NN * DD];    // 8 MB, int8 of 256*A
__device__ int8_t g_B8[(size_t)NN * DD];    // 8 MB, int8 of 256*B
__device__ float g_c[NN], g_c2[NN];
__device__ float g_r[NN], g_r2[NN];
__device__ float g_u[NN], g_u2[NN];   // row sums; reused as CE S accumulators
__device__ float g_s[NN], g_s2[NN];   // col sums
__device__ float g_diag[NN], g_diag2[NN];
__device__ float g_sums[1];

// ---------------- fp8 helpers ----------------
__device__ __forceinline__ unsigned short f32x2_to_e4m3x2(float lo, float hi) {
    unsigned short r;
    asm("cvt.rn.satfinite.e4m3x2.f32 %0, %1, %2;" : "=h"(r) : "f"(hi), "f"(lo));
    return r;
}
__device__ __forceinline__ __half2 e4m3x2_to_h2(unsigned short s) {
    uint32_t h;
    asm("cvt.rn.f16x2.e4m3x2 %0, %1;" : "=r"(h) : "h"(s));
    return *reinterpret_cast<__half2*>(&h);
}
__device__ __forceinline__ float e4m3_byte_to_f32(uint8_t b) {
    return __low2float(e4m3x2_to_h2((unsigned short)b));
}
__device__ __forceinline__ __half2 shfl_down_h2(__half2 v, int o) {
    uint32_t u = *reinterpret_cast<uint32_t*>(&v);
    u = __shfl_down_sync(0xffffffffu, u, o);
    return *reinterpret_cast<__half2*>(&u);
}
__device__ __forceinline__ uint32_t ldg_u32_nc(const uint8_t* p) {
    uint32_t u;
    asm volatile("ld.global.nc.u32 %0, [%1];" : "=r"(u) : "l"(p));
    return u;
}

// ---------------- init ----------------
__global__ void init_kernel() {
    int i = blockIdx.x * blockDim.x + threadIdx.x;
    if (i < NN) {
        g_c[i] = 1.0f; g_c2[i] = 1.0f;
        g_u[i] = 0.0f; g_u2[i] = 0.0f;
        g_s[i] = 0.0f; g_s2[i] = 0.0f;
    }
    if (i == 0) g_sums[0] = 0.0f;
}

// ---------------- fp32 -> int8 convert (scale 256) ----------------
__device__ __forceinline__ uint32_t quant4(float4 v) {
    int i0 = __float2int_rn(fminf(fmaxf(v.x * INSCALE, -127.f), 127.f));
    int i1 = __float2int_rn(fminf(fmaxf(v.y * INSCALE, -127.f), 127.f));
    int i2 = __float2int_rn(fminf(fmaxf(v.z * INSCALE, -127.f), 127.f));
    int i3 = __float2int_rn(fminf(fmaxf(v.w * INSCALE, -127.f), 127.f));
    return (uint32_t)(i0 & 255) | ((uint32_t)(i1 & 255) << 8) |
           ((uint32_t)(i2 & 255) << 16) | ((uint32_t)(i3 & 255) << 24);
}
__global__ __launch_bounds__(256) void convert_kernel(
    const float* __restrict__ A, const float* __restrict__ B) {
    int i = blockIdx.x * blockDim.x + threadIdx.x;  // float4 index
    const int n4 = NN * DD / 4;
    if (i < n4) {
        reinterpret_cast<uint32_t*>(g_A8)[i] =
            quant4(reinterpret_cast<const float4*>(A)[i]);
        reinterpret_cast<uint32_t*>(g_B8)[i] =
            quant4(reinterpret_cast<const float4*>(B)[i]);
    }
}

// ---------------- int8 tensor-core GEMM: P0 = e4m3(exp(acc/65536 - 1)) ------
// Epilogue ALSO accumulates exact f32 row sums -> g_u and col sums -> g_u2
// (Sinkhorn iteration 1 has c = c2 = 1, so this IS pass1 of iteration 1).
constexpr int KSTG = 128;                 // K elements (bytes) per stage
constexpr int KT = DD / KSTG;             // 8
constexpr int STAGE_BYTES = 2 * 128 * 128;  // A tile + B tile = 32KB
constexpr int B_OFF = 128 * 128;            // 16KB

__device__ __forceinline__ void cp_async16(uint32_t s, const void* g) {
    asm volatile("cp.async.cg.shared.global [%0], [%1], 16;\n" :: "r"(s), "l"(g));
}
__device__ __forceinline__ void cp_commit() {
    asm volatile("cp.async.commit_group;\n");
}
template <int N>
__device__ __forceinline__ void cp_wait() {
    asm volatile("cp.async.wait_group %0;\n" :: "n"(N));
}
__device__ __forceinline__ void ldsm4(uint32_t& r0, uint32_t& r1, uint32_t& r2,
                                      uint32_t& r3, uint32_t addr) {
    asm volatile("ldmatrix.sync.aligned.m8n8.x4.shared.b16 {%0,%1,%2,%3}, [%4];\n"
                 : "=r"(r0), "=r"(r1), "=r"(r2), "=r"(r3) : "r"(addr));
}
__device__ __forceinline__ void mma16832_s8(int* c, const uint32_t* a,
                                            const uint32_t* b) {
    asm volatile(
        "mma.sync.aligned.m16n8k32.row.col.s32.s8.s8.s32 "
        "{%0,%1,%2,%3}, {%4,%5,%6,%7}, {%8,%9}, {%0,%1,%2,%3};\n"
        : "+r"(c[0]), "+r"(c[1]), "+r"(c[2]), "+r"(c[3])
        : "r"(a[0]), "r"(a[1]), "r"(a[2]), "r"(a[3]), "r"(b[0]), "r"(b[1]));
}

__global__ __launch_bounds__(256) void gemm_i8_exp_kernel() {
    extern __shared__ char smem[];
    const uint32_t sbase = (uint32_t)__cvta_generic_to_shared(smem);
    const int tid = threadIdx.x;
    const int wid = tid >> 5;
    const int lane = tid & 31;
    const int warp_m = wid & 1;   // 0..1, 64 rows each
    const int warp_n = wid >> 1;  // 0..3, 32 cols each
    const int bi = blockIdx.y * 128;
    const int bj = blockIdx.x * 128;

    int acc[4][4][4];
#pragma unroll
    for (int mt = 0; mt < 4; mt++)
#pragma unroll
        for (int nt = 0; nt < 4; nt++)
#pragma unroll
            for (int r = 0; r < 4; r++) acc[mt][nt][r] = 0;

    auto load_stage = [&](int kt, int stage) {
        const int k0 = kt * KSTG;
        const uint32_t so = sbase + stage * STAGE_BYTES;
#pragma unroll
        for (int i = 0; i < 4; i++) {
            int u = tid + i * 256;   // 1024 16B units per tile
            int row = u >> 3;
            int chunk = u & 7;
            uint32_t d = so + row * 128 + ((chunk * 16) ^ ((row & 7) << 4));
            cp_async16(d, &g_A8[(size_t)(bi + row) * DD + k0 + chunk * 16]);
            cp_async16(d + B_OFF, &g_B8[(size_t)(bj + row) * DD + k0 + chunk * 16]);
        }
        cp_commit();
    };

    load_stage(0, 0);

    for (int kt = 0; kt < KT; kt++) {
        const int stage = kt & 1;
        if (kt + 1 < KT) {
            load_stage(kt + 1, stage ^ 1);
            cp_wait<1>();
        } else {
            cp_wait<0>();
        }
        __syncthreads();

        const uint32_t sa = sbase + stage * STAGE_BYTES;
        const uint32_t sb = sa + B_OFF;
#pragma unroll
        for (int kk = 0; kk < 4; kk++) {   // each kk: K=32 int8 = 2 chunks
            uint32_t a[4][4];
#pragma unroll
            for (int mt = 0; mt < 4; mt++) {
                int row = warp_m * 64 + mt * 16 + (lane & 15);
                int chunk = kk * 2 + (lane >> 4);
                uint32_t addr = sa + row * 128 + ((chunk * 16) ^ ((row & 7) << 4));
                ldsm4(a[mt][0], a[mt][1], a[mt][2], a[mt][3], addr);
            }
            uint32_t b[2][4];
#pragma unroll
            for (int pair = 0; pair < 2; pair++) {
                int rown = warp_n * 32 + pair * 16 + ((lane >> 4) << 3) + (lane & 7);
                int chunk = kk * 2 + ((lane >> 3) & 1);
                uint32_t addr = sb + rown * 128 + ((chunk * 16) ^ ((rown & 7) << 4));
                ldsm4(b[pair][0], b[pair][1], b[pair][2], b[pair][3], addr);
            }
#pragma unroll
            for (int mt = 0; mt < 4; mt++)
#pragma unroll
                for (int nt = 0; nt < 4; nt++)
                    mma16832_s8(acc[mt][nt], a[mt], &b[nt >> 1][(nt & 1) * 2]);
        }
        __syncthreads();
    }

    // Epilogue stage 1: exp(acc/65536 - 1) -> e4m3 smem tile + f32 row/col sums
    const int lrow = lane >> 2;
    const int lcol = (lane & 3) * 2;
    float rowacc[8], colacc[8];
#pragma unroll
    for (int k = 0; k < 8; k++) { rowacc[k] = 0.f; colacc[k] = 0.f; }
#pragma unroll
    for (int mt = 0; mt < 4; mt++) {
#pragma unroll
        for (int nt = 0; nt < 4; nt++) {
            int r0 = warp_m * 64 + mt * 16 + lrow;
            int cc = warp_n * 32 + nt * 8 + lcol;
            float e0 = __expf(__int2float_rn(acc[mt][nt][0]) * ACCSCALE - 1.0f);
            float e1 = __expf(__int2float_rn(acc[mt][nt][1]) * ACCSCALE - 1.0f);
            float e2 = __expf(__int2float_rn(acc[mt][nt][2]) * ACCSCALE - 1.0f);
            float e3 = __expf(__int2float_rn(acc[mt][nt][3]) * ACCSCALE - 1.0f);
            rowacc[mt * 2 + 0] += e0 + e1;   // row r0
            rowacc[mt * 2 + 1] += e2 + e3;   // row r0 + 8
            colacc[nt * 2 + 0] += e0 + e2;   // col cc
            colacc[nt * 2 + 1] += e1 + e3;   // col cc + 1
            unsigned short p0 = f32x2_to_e4m3x2(e0, e1);
            unsigned short p1 = f32x2_to_e4m3x2(e2, e3);
            *reinterpret_cast<unsigned short*>(smem + r0 * 128 + cc) = p0;
            *reinterpret_cast<unsigned short*>(smem + (r0 + 8) * 128 + cc) = p1;
        }
    }
    // row sums: lanes within a quad (same lrow) hold disjoint cols -> reduce
#pragma unroll
    for (int k = 0; k < 8; k++) {
        rowacc[k] += __shfl_down_sync(0xffffffffu, rowacc[k], 2);
        rowacc[k] += __shfl_down_sync(0xffffffffu, rowacc[k], 1);
    }
    if ((lane & 3) == 0) {
#pragma unroll
        for (int mt = 0; mt < 4; mt++) {
            atomicAdd(&g_u[bi + warp_m * 64 + mt * 16 + lrow], rowacc[mt * 2]);
            atomicAdd(&g_u[bi + warp_m * 64 + mt * 16 + 8 + lrow],
                      rowacc[mt * 2 + 1]);
        }
    }
    // col sums: stride-4 lanes (same lane&3) hold disjoint rows -> reduce
#pragma unroll
    for (int k = 0; k < 8; k++) {
        colacc[k] += __shfl_down_sync(0xffffffffu, colacc[k], 16);
        colacc[k] += __shfl_down_sync(0xffffffffu, colacc[k], 8);
        colacc[k] += __shfl_down_sync(0xffffffffu, colacc[k], 4);
    }
    if (lane < 4) {
#pragma unroll
        for (int nt = 0; nt < 4; nt++) {
            atomicAdd(&g_u2[bj + warp_n * 32 + nt * 8 + lane * 2],
                      colacc[nt * 2]);
            atomicAdd(&g_u2[bj + warp_n * 32 + nt * 8 + lane * 2 + 1],
                      colacc[nt * 2 + 1]);
        }
    }
    __syncthreads();

    // Epilogue stage 2: coalesced uint4 stores
    {
        const uint4* st = reinterpret_cast<const uint4*>(smem);
        int base = tid * 4;             // uint4 index
        int row = base >> 3;            // 8 uint4 per 128B row
        int coloff = (base & 7) * 16;   // byte offset in row
        uint4* gp = reinterpret_cast<uint4*>(
            &g_P0[(size_t)(bi + row) * NN + bj + coloff]);
#pragma unroll
        for (int q = 0; q < 4; q++) gp[q] = st[base + q];
    }
}

// ---------------- fused dual matvec: proven shape + half2 + load prefetch ---
template <bool RECIP>
__global__ __launch_bounds__(256) void dual_matvec_kernel(
    const float* __restrict__ a, const float* __restrict__ b,
    float* __restrict__ out_row, float* __restrict__ out_col) {
    const int ROWS = 64;
    const int tid = threadIdx.x;
    const int j = (blockIdx.x * 256 + tid) * 4;
    const int i0 = blockIdx.y * ROWS;
    __shared__ __half2 bsh[ROWS];
    __shared__ float rowpart[ROWS][9];
    const float a0 = a[0];
    const float b0 = b[0];
    if (tid < ROWS) {
        float v = b[i0 + tid];
        float w = RECIP ? (b0 / v) : (v / b0);
        bsh[tid] = __float2half2_rn(w);
    }
    __syncthreads();

    __half2 ah01, ah23;
    {
        float4 t = *reinterpret_cast<const float4*>(&a[j]);
        float x0 = RECIP ? (a0 / t.x) : (t.x / a0);
        float x1 = RECIP ? (a0 / t.y) : (t.y / a0);
        float x2 = RECIP ? (a0 / t.z) : (t.z / a0);
        float x3 = RECIP ? (a0 / t.w) : (t.w / a0);
        ah01 = __floats2half2_rn(x0, x1);
        ah23 = __floats2half2_rn(x2, x3);
    }
    float c0 = 0.f, c1 = 0.f, c2 = 0.f, c3 = 0.f;   // f32 column totals
    const int warp = tid >> 5, lane = tid & 31;
    const uint8_t* base = g_P0 + (size_t)i0 * NN + j;

    const __half2 zero2 = __floats2half2_rn(0.f, 0.f);
    uint32_t pu0 = ldg_u32_nc(base);
    uint32_t pu1 = ldg_u32_nc(base + NN);
#pragma unroll
    for (int chunk = 0; chunk < 2; chunk++) {       // 2 x 32-row chunks
        __half2 cacc01 = zero2, cacc23 = zero2;
#pragma unroll 4
        for (int it2 = 0; it2 < 16; it2++) {
            const int ii = chunk * 32 + it2 * 2;
            const uint32_t u0 = pu0;
            const uint32_t u1 = pu1;
            if (ii + 2 < ROWS) {   // prefetch next pair before compute
                pu0 = ldg_u32_nc(base + (size_t)(ii + 2) * NN);
                pu1 = ldg_u32_nc(base + (size_t)(ii + 3) * NN);
            }
            __half2 v0a = e4m3x2_to_h2((unsigned short)(u0 & 0xffffu));
            __half2 v0b = e4m3x2_to_h2((unsigned short)(u0 >> 16));
            __half2 v1a = e4m3x2_to_h2((unsigned short)(u1 & 0xffffu));
            __half2 v1b = e4m3x2_to_h2((unsigned short)(u1 >> 16));
            __half2 bb0 = bsh[ii], bb1 = bsh[ii + 1];
            cacc01 = __hfma2(v0a, bb0, cacc01);
            cacc23 = __hfma2(v0b, bb0, cacc23);
            cacc01 = __hfma2(v1a, bb1, cacc01);
            cacc23 = __hfma2(v1b, bb1, cacc23);
            __half2 d0 = __hfma2(v0b, ah23, __hmul2(v0a, ah01));
            __half2 d1 = __hfma2(v1b, ah23, __hmul2(v1a, ah01));
            __half2 lo = __halves2half2(__low2half(d0), __low2half(d1));
            __half2 hi = __halves2half2(__high2half(d0), __high2half(d1));
            __half2 dd = __hadd2(lo, hi);
#pragma unroll
            for (int o = 16; o > 0; o >>= 1)
                dd = __hadd2(dd, shfl_down_h2(dd, o));
            if (lane == 0) {
                rowpart[ii][warp] = __low2float(dd);
                rowpart[ii + 1][warp] = __high2float(dd);
            }
        }
        c0 += __low2float(cacc01); c1 += __high2float(cacc01);
        c2 += __low2float(cacc23); c3 += __high2float(cacc23);
    }
    __syncthreads();
    const float s_a = RECIP ? (1.0f / a0) : a0;
    const float s_b = RECIP ? (1.0f / b0) : b0;
    if (tid < ROWS) {
        float sacc = 0.f;
#pragma unroll
        for (int w = 0; w < 8; w++) sacc += rowpart[tid][w];
        atomicAdd(&out_row[i0 + tid], sacc * s_a);
    }
    atomicAdd(&out_col[j + 0], c0 * s_b);
    atomicAdd(&out_col[j + 1], c1 * s_b);
    atomicAdd(&out_col[j + 2], c2 * s_b);
    atomicAdd(&out_col[j + 3], c3 * s_b);
}

// colupd: r = 1/u (persists for CE), c/c2 two-step update from s/s2,
// then zero u,u2,s,s2 for next iteration / CE accumulators.
__global__ void colupd_kernel() {
    int i = blockIdx.x * blockDim.x + threadIdx.x;
    if (i < NN) {
        g_r[i] = 1.0f / g_u[i];
        g_r2[i] = 1.0f / g_u2[i];
        float cv = g_c[i], sv = g_s[i];
        cv *= fmaxf(BD / (cv * sv), 1.0f);
        cv *= fminf(BU / (cv * sv), 1.0f);
        g_c[i] = cv;
        float cv2 = g_c2[i], sv2 = g_s2[i];
        cv2 *= fmaxf(BD / (cv2 * sv2), 1.0f);
        cv2 *= fminf(BU / (cv2 * sv2), 1.0f);
        g_c2[i] = cv2;
        g_u[i] = 0.0f; g_u2[i] = 0.0f;
        g_s[i] = 0.0f; g_s2[i] = 0.0f;
    }
}

// ---------------- diag terms ----------------
__global__ __launch_bounds__(256) void diag_kernel(const int* __restrict__ labels) {
    int i = blockIdx.x * 256 + threadIdx.x;
    int lab = labels[i];
    float v1 = e4m3_byte_to_f32(g_P0[(size_t)i * NN + lab]);
    g_diag[i] = g_r[i] * v1 * g_c[lab];
    float v2 = e4m3_byte_to_f32(g_P0[(size_t)lab * NN + i]);
    g_diag2[i] = g_r2[i] * v2 * g_c2[lab];
}

// ---------------- fused CE: both logsumexps in ONE read of P0, half2 exp ----
__global__ __launch_bounds__(256) void ce_fused_kernel() {
    const int ROWS = 64;
    const int tid = threadIdx.x;
    const int j = (blockIdx.x * 256 + tid) * 4;
    const int i0 = blockIdx.y * ROWS;
    __shared__ __half2 Fsh[ROWS];   // r_i * c0
    __shared__ __half2 Csh[ROWS];   // c2_i / c2_0
    __shared__ float rowpart[ROWS][9];
    const float c0 = g_c[0];
    const float c20 = g_c2[0];
    if (tid < ROWS) {
        Fsh[tid] = __float2half2_rn(g_r[i0 + tid] * c0);
        Csh[tid] = __float2half2_rn(g_c2[i0 + tid] / c20);
    }
    __syncthreads();

    __half2 cn01, cn23, G01, G23;
    {
        float4 cv = *reinterpret_cast<const float4*>(&g_c[j]);
        float4 rv = *reinterpret_cast<const float4*>(&g_r2[j]);
        cn01 = __floats2half2_rn(cv.x / c0, cv.y / c0);
        cn23 = __floats2half2_rn(cv.z / c0, cv.w / c0);
        G01 = __floats2half2_rn(rv.x * c20, rv.y * c20);
        G23 = __floats2half2_rn(rv.z * c20, rv.w * c20);
    }
    const __half2 zero2 = __floats2half2_rn(0.f, 0.f);
    __half2 colacc01 = zero2, colacc23 = zero2;
    const int warp = tid >> 5, lane = tid & 31;
    const uint8_t* base = g_P0 + (size_t)i0 * NN + j;

    uint32_t pu0 = ldg_u32_nc(base);
    uint32_t pu1 = ldg_u32_nc(base + NN);
    for (int ii = 0; ii < ROWS; ii += 2) {
        const uint32_t u0 = pu0;
        const uint32_t u1 = pu1;
        if (ii + 2 < ROWS) {
            pu0 = ldg_u32_nc(base + (size_t)(ii + 2) * NN);
            pu1 = ldg_u32_nc(base + (size_t)(ii + 3) * NN);
        }
        __half2 v0a = e4m3x2_to_h2((unsigned short)(u0 & 0xffffu));
        __half2 v0b = e4m3x2_to_h2((unsigned short)(u0 >> 16));
        __half2 v1a = e4m3x2_to_h2((unsigned short)(u1 & 0xffffu));
        __half2 v1b = e4m3x2_to_h2((unsigned short)(u1 >> 16));
        __half2 F0 = Fsh[ii], F1 = Fsh[ii + 1];
        __half2 C0 = Csh[ii], C1 = Csh[ii + 1];
        __half2 x0 = __hadd2(h2exp(__hmul2(__hmul2(F0, cn01), v0a)),
                             h2exp(__hmul2(__hmul2(F0, cn23), v0b)));
        __half2 x1 = __hadd2(h2exp(__hmul2(__hmul2(F1, cn01), v1a)),
                             h2exp(__hmul2(__hmul2(F1, cn23), v1b)));
        colacc01 = __hadd2(colacc01, h2exp(__hmul2(__hmul2(G01, C0), v0a)));
        colacc23 = __hadd2(colacc23, h2exp(__hmul2(__hmul2(G23, C0), v0b)));
        colacc01 = __hadd2(colacc01, h2exp(__hmul2(__hmul2(G01, C1), v1a)));
        colacc23 = __hadd2(colacc23, h2exp(__hmul2(__hmul2(G23, C1), v1b)));
        __half2 lo = __halves2half2(__low2half(x0), __low2half(x1));
        __half2 hi = __halves2half2(__high2half(x0), __high2half(x1));
        __half2 dd = __hadd2(lo, hi);
#pragma unroll
        for (int o = 16; o > 0; o >>= 1)
            dd = __hadd2(dd, shfl_down_h2(dd, o));
        if (lane == 0) {
            rowpart[ii][warp] = __low2float(dd);
            rowpart[ii + 1][warp] = __high2float(dd);
        }
    }
    __syncthreads();
    if (tid < ROWS) {
        float sacc = 0.f;
#pragma unroll
        for (int w = 0; w < 8; w++) sacc += rowpart[tid][w];
        atomicAdd(&g_u[i0 + tid], sacc);
    }
    atomicAdd(&g_u2[j + 0], __low2float(colacc01));
    atomicAdd(&g_u2[j + 1], __high2float(colacc01));
    atomicAdd(&g_u2[j + 2], __low2float(colacc23));
    atomicAdd(&g_u2[j + 3], __high2float(colacc23));
}

__global__ __launch_bounds__(256) void ce_reduce_kernel() {
    int t = blockIdx.x * 256 + threadIdx.x;
    float v = (logf(g_u[t]) - g_diag[t]) + (logf(g_u2[t]) - g_diag2[t]);
    __shared__ float wsum[8];
#pragma unroll
    for (int o = 16; o > 0; o >>= 1)
        v += __shfl_down_sync(0xffffffffu, v, o);
    int warp = threadIdx.x >> 5, lane = threadIdx.x & 31;
    if (lane == 0) wsum[warp] = v;
    __syncthreads();
    if (threadIdx.x == 0) {
        float tt = 0.f;
#pragma unroll
        for (int w = 0; w < 8; w++) tt += wsum[w];
        atomicAdd(&g_sums[0], tt);
    }
}

__global__ void finalize_kernel(float* __restrict__ out) {
    out[0] = g_sums[0] / (2.0f * (float)NN);
}

// ---------------- launch ----------------
extern "C" void kernel_launch(void* const* d_in, const int* in_sizes, int n_in,
                              void* d_out, int out_size) {
    const float* A = (const float*)d_in[0];   // all_image_features [N, D]
    const float* B = (const float*)d_in[1];   // all_text_features  [N, D]
    const int* labels = (const int*)d_in[3];
    float* out = (float*)d_out;

    float *c, *c2, *u, *u2, *s, *s2;
    cudaGetSymbolAddress((void**)&c, g_c);
    cudaGetSymbolAddress((void**)&c2, g_c2);
    cudaGetSymbolAddress((void**)&u, g_u);
    cudaGetSymbolAddress((void**)&u2, g_u2);
    cudaGetSymbolAddress((void**)&s, g_s);
    cudaGetSymbolAddress((void**)&s2, g_s2);

    cudaFuncSetAttribute(gemm_i8_exp_kernel,
                         cudaFuncAttributeMaxDynamicSharedMemorySize,
                         2 * STAGE_BYTES);

    init_kernel<<<NN / 256, 256>>>();
    convert_kernel<<<NN * DD / 4 / 256, 256>>>(A, B);
    // GEMM epilogue also produces u = rowsum(P0), u2 = colsum(P0)
    // (== Sinkhorn iteration-1 pass1, since c = c2 = 1 initially)
    gemm_i8_exp_kernel<<<dim3(64, 64), 256, 2 * STAGE_BYTES>>>();

    for (int it = 0; it < 5; it++) {
        // pass2: s2_i += sum_j P0_ij (1/u2_j) ; s_j += sum_i P0_ij (1/u_i)
        dual_matvec_kernel<true><<<dim3(8, 128), 256>>>(u2, u, s2, s);
        colupd_kernel<<<NN / 256, 256>>>();
        if (it < 4) {
            // pass1: u_i += sum_j P0_ij c_j ; u2_j += sum_i P0_ij c2_i
            dual_matvec_kernel<false><<<dim3(8, 128), 256>>>(c, c2, u, u2);
        }
    }

    diag_kernel<<<NN / 256, 256>>>(labels);
    ce_fused_kernel<<<dim3(8, 128), 256>>>();
    ce_reduce_kernel<<<NN / 256, 256>>>();
    finalize_kernel<<<1, 1>>>(out);
}

// round 16
// speedup vs baseline: 1.6856x; 1.0215x over previous
#include <cuda_runtime.h>
#include <cuda_bf16.h>
#include <cuda_fp16.h>
#include <math.h>
#include <stdint.h>

// Problem constants
constexpr int NN = 8192;
constexpr int DD = 1024;
constexpr float BD = 819.2f;   // 0.1 * n
constexpr float BU = 7372.8f;  // 0.9 * n
constexpr float INSCALE = 256.0f;            // int8 quantization scale
constexpr float ACCSCALE = 1.0f / 65536.0f;  // 1/(256*256)

// ---------------- device scratch (static, allocation-free) ----------------
__device__ uint8_t g_P0[(size_t)NN * NN];   // 64 MB, e4m3 of exp(L - 1)
__device__ int8_t g_A8[(size_t)NN * DD];    // 8 MB, int8 of 256*A
__device__ int8_t g_B8[(size_t)NN * DD];    // 8 MB, int8 of 256*B
__device__ float g_c[NN], g_c2[NN];
__device__ float g_r[NN], g_r2[NN];
__device__ float g_u[NN], g_u2[NN];   // row sums; reused as CE S accumulators
__device__ float g_s[NN], g_s2[NN];   // col sums
__device__ float g_diag[NN], g_diag2[NN];
__device__ float g_sums[1];

// ---------------- fp8 helpers ----------------
__device__ __forceinline__ unsigned short f32x2_to_e4m3x2(float lo, float hi) {
    unsigned short r;
    asm("cvt.rn.satfinite.e4m3x2.f32 %0, %1, %2;" : "=h"(r) : "f"(hi), "f"(lo));
    return r;
}
__device__ __forceinline__ __half2 e4m3x2_to_h2(unsigned short s) {
    uint32_t h;
    asm("cvt.rn.f16x2.e4m3x2 %0, %1;" : "=r"(h) : "h"(s));
    return *reinterpret_cast<__half2*>(&h);
}
__device__ __forceinline__ float e4m3_byte_to_f32(uint8_t b) {
    return __low2float(e4m3x2_to_h2((unsigned short)b));
}
__device__ __forceinline__ __half2 shfl_down_h2(__half2 v, int o) {
    uint32_t u = *reinterpret_cast<uint32_t*>(&v);
    u = __shfl_down_sync(0xffffffffu, u, o);
    return *reinterpret_cast<__half2*>(&u);
}
__device__ __forceinline__ uint32_t ldg_u32_nc(const uint8_t* p) {
    uint32_t u;
    asm volatile("ld.global.nc.u32 %0, [%1];" : "=r"(u) : "l"(p));
    return u;
}

// ---------------- init ----------------
__global__ void init_kernel() {
    int i = blockIdx.x * blockDim.x + threadIdx.x;
    if (i < NN) {
        g_c[i] = 1.0f; g_c2[i] = 1.0f;
        g_u[i] = 0.0f; g_u2[i] = 0.0f;
        g_s[i] = 0.0f; g_s2[i] = 0.0f;
    }
    if (i == 0) g_sums[0] = 0.0f;
}

// ---------------- fp32 -> int8 convert (scale 256) ----------------
__device__ __forceinline__ uint32_t quant4(float4 v) {
    int i0 = __float2int_rn(fminf(fmaxf(v.x * INSCALE, -127.f), 127.f));
    int i1 = __float2int_rn(fminf(fmaxf(v.y * INSCALE, -127.f), 127.f));
    int i2 = __float2int_rn(fminf(fmaxf(v.z * INSCALE, -127.f), 127.f));
    int i3 = __float2int_rn(fminf(fmaxf(v.w * INSCALE, -127.f), 127.f));
    return (uint32_t)(i0 & 255) | ((uint32_t)(i1 & 255) << 8) |
           ((uint32_t)(i2 & 255) << 16) | ((uint32_t)(i3 & 255) << 24);
}
__global__ __launch_bounds__(256) void convert_kernel(
    const float* __restrict__ A, const float* __restrict__ B) {
    int i = blockIdx.x * blockDim.x + threadIdx.x;  // float4 index
    const int n4 = NN * DD / 4;
    if (i < n4) {
        reinterpret_cast<uint32_t*>(g_A8)[i] =
            quant4(reinterpret_cast<const float4*>(A)[i]);
        reinterpret_cast<uint32_t*>(g_B8)[i] =
            quant4(reinterpret_cast<const float4*>(B)[i]);
    }
}

// ---------------- int8 tensor-core GEMM: P0 = e4m3(exp(acc/65536 - 1)) ------
// Epilogue ALSO produces iteration-1 pass1 sums: u = rowsum, u2 = colsum
// (c = c2 = 1 at iteration 1). Col sums: 4 packed half2 regs in stage 1.
// Row sums: decoded from the smem fp8 tile in stage 2 (no mainloop regs).
constexpr int KSTG = 128;                 // K elements (bytes) per stage
constexpr int KT = DD / KSTG;             // 8
constexpr int STAGE_BYTES = 2 * 128 * 128;  // A tile + B tile = 32KB
constexpr int B_OFF = 128 * 128;            // 16KB

__device__ __forceinline__ void cp_async16(uint32_t s, const void* g) {
    asm volatile("cp.async.cg.shared.global [%0], [%1], 16;\n" :: "r"(s), "l"(g));
}
__device__ __forceinline__ void cp_commit() {
    asm volatile("cp.async.commit_group;\n");
}
template <int N>
__device__ __forceinline__ void cp_wait() {
    asm volatile("cp.async.wait_group %0;\n" :: "n"(N));
}
__device__ __forceinline__ void ldsm4(uint32_t& r0, uint32_t& r1, uint32_t& r2,
                                      uint32_t& r3, uint32_t addr) {
    asm volatile("ldmatrix.sync.aligned.m8n8.x4.shared.b16 {%0,%1,%2,%3}, [%4];\n"
                 : "=r"(r0), "=r"(r1), "=r"(r2), "=r"(r3) : "r"(addr));
}
__device__ __forceinline__ void mma16832_s8(int* c, const uint32_t* a,
                                            const uint32_t* b) {
    asm volatile(
        "mma.sync.aligned.m16n8k32.row.col.s32.s8.s8.s32 "
        "{%0,%1,%2,%3}, {%4,%5,%6,%7}, {%8,%9}, {%0,%1,%2,%3};\n"
        : "+r"(c[0]), "+r"(c[1]), "+r"(c[2]), "+r"(c[3])
        : "r"(a[0]), "r"(a[1]), "r"(a[2]), "r"(a[3]), "r"(b[0]), "r"(b[1]));
}

__global__ __launch_bounds__(256) void gemm_i8_exp_kernel() {
    extern __shared__ char smem[];
    const uint32_t sbase = (uint32_t)__cvta_generic_to_shared(smem);
    const int tid = threadIdx.x;
    const int wid = tid >> 5;
    const int lane = tid & 31;
    const int warp_m = wid & 1;   // 0..1, 64 rows each
    const int warp_n = wid >> 1;  // 0..3, 32 cols each
    const int bi = blockIdx.y * 128;
    const int bj = blockIdx.x * 128;

    int acc[4][4][4];
#pragma unroll
    for (int mt = 0; mt < 4; mt++)
#pragma unroll
        for (int nt = 0; nt < 4; nt++)
#pragma unroll
            for (int r = 0; r < 4; r++) acc[mt][nt][r] = 0;

    auto load_stage = [&](int kt, int stage) {
        const int k0 = kt * KSTG;
        const uint32_t so = sbase + stage * STAGE_BYTES;
#pragma unroll
        for (int i = 0; i < 4; i++) {
            int u = tid + i * 256;   // 1024 16B units per tile
            int row = u >> 3;
            int chunk = u & 7;
            uint32_t d = so + row * 128 + ((chunk * 16) ^ ((row & 7) << 4));
            cp_async16(d, &g_A8[(size_t)(bi + row) * DD + k0 + chunk * 16]);
            cp_async16(d + B_OFF, &g_B8[(size_t)(bj + row) * DD + k0 + chunk * 16]);
        }
        cp_commit();
    };

    load_stage(0, 0);

    for (int kt = 0; kt < KT; kt++) {
        const int stage = kt & 1;
        if (kt + 1 < KT) {
            load_stage(kt + 1, stage ^ 1);
            cp_wait<1>();
        } else {
            cp_wait<0>();
        }
        __syncthreads();

        const uint32_t sa = sbase + stage * STAGE_BYTES;
        const uint32_t sb = sa + B_OFF;
#pragma unroll
        for (int kk = 0; kk < 4; kk++) {   // each kk: K=32 int8 = 2 chunks
            uint32_t a[4][4];
#pragma unroll
            for (int mt = 0; mt < 4; mt++) {
                int row = warp_m * 64 + mt * 16 + (lane & 15);
                int chunk = kk * 2 + (lane >> 4);
                uint32_t addr = sa + row * 128 + ((chunk * 16) ^ ((row & 7) << 4));
                ldsm4(a[mt][0], a[mt][1], a[mt][2], a[mt][3], addr);
            }
            uint32_t b[2][4];
#pragma unroll
            for (int pair = 0; pair < 2; pair++) {
                int rown = warp_n * 32 + pair * 16 + ((lane >> 4) << 3) + (lane & 7);
                int chunk = kk * 2 + ((lane >> 3) & 1);
                uint32_t addr = sb + rown * 128 + ((chunk * 16) ^ ((rown & 7) << 4));
                ldsm4(b[pair][0], b[pair][1], b[pair][2], b[pair][3], addr);
            }
#pragma unroll
            for (int mt = 0; mt < 4; mt++)
#pragma unroll
                for (int nt = 0; nt < 4; nt++)
                    mma16832_s8(acc[mt][nt], a[mt], &b[nt >> 1][(nt & 1) * 2]);
        }
        __syncthreads();
    }

    // Epilogue stage 1: exp(acc/65536 - 1) -> e4m3 smem tile.
    // Col partial sums in 4 packed half2 regs (low = col cc, high = cc+1).
    const int lrow = lane >> 2;
    const int lcol = (lane & 3) * 2;
    __half2 colacc[4];
#pragma unroll
    for (int k = 0; k < 4; k++) colacc[k] = __floats2half2_rn(0.f, 0.f);
#pragma unroll
    for (int mt = 0; mt < 4; mt++) {
#pragma unroll
        for (int nt = 0; nt < 4; nt++) {
            int r0 = warp_m * 64 + mt * 16 + lrow;
            int cc = warp_n * 32 + nt * 8 + lcol;
            float e0 = __expf(__int2float_rn(acc[mt][nt][0]) * ACCSCALE - 1.0f);
            float e1 = __expf(__int2float_rn(acc[mt][nt][1]) * ACCSCALE - 1.0f);
            float e2 = __expf(__int2float_rn(acc[mt][nt][2]) * ACCSCALE - 1.0f);
            float e3 = __expf(__int2float_rn(acc[mt][nt][3]) * ACCSCALE - 1.0f);
            colacc[nt] = __hadd2(colacc[nt], __floats2half2_rn(e0 + e2, e1 + e3));
            unsigned short p0 = f32x2_to_e4m3x2(e0, e1);
            unsigned short p1 = f32x2_to_e4m3x2(e2, e3);
            *reinterpret_cast<unsigned short*>(smem + r0 * 128 + cc) = p0;
            *reinterpret_cast<unsigned short*>(smem + (r0 + 8) * 128 + cc) = p1;
        }
    }
    // col sums: stride-4 lanes (same lane&3) hold disjoint rows -> reduce
#pragma unroll
    for (int k = 0; k < 4; k++) {
        colacc[k] = __hadd2(colacc[k], shfl_down_h2(colacc[k], 16));
        colacc[k] = __hadd2(colacc[k], shfl_down_h2(colacc[k], 8));
        colacc[k] = __hadd2(colacc[k], shfl_down_h2(colacc[k], 4));
    }
    if (lane < 4) {
#pragma unroll
        for (int nt = 0; nt < 4; nt++) {
            float2 f = __half22float2(colacc[nt]);
            atomicAdd(&g_u2[bj + warp_n * 32 + nt * 8 + lane * 2], f.x);
            atomicAdd(&g_u2[bj + warp_n * 32 + nt * 8 + lane * 2 + 1], f.y);
        }
    }
    __syncthreads();

    // Epilogue stage 2: coalesced stores + row sums from the fp8 tile.
    // Thread t covers 64 consecutive bytes of row t/2 (threads 2t, 2t+1 pair).
    {
        const uint4* st = reinterpret_cast<const uint4*>(smem);
        int base = tid * 4;             // uint4 index
        int row = base >> 3;            // 8 uint4 per 128B row
        int coloff = (base & 7) * 16;   // byte offset in row
        uint4* gp = reinterpret_cast<uint4*>(
            &g_P0[(size_t)(bi + row) * NN + bj + coloff]);
        __half2 hs[16];
#pragma unroll
        for (int q = 0; q < 4; q++) {
            uint4 v = st[base + q];
            gp[q] = v;
            hs[q * 4 + 0] = e4m3x2_to_h2((unsigned short)(v.x & 0xffffu));
            hs[q * 4 + 1] = e4m3x2_to_h2((unsigned short)(v.x >> 16));
            hs[q * 4 + 2] = e4m3x2_to_h2((unsigned short)(v.y & 0xffffu));
            hs[q * 4 + 3] = e4m3x2_to_h2((unsigned short)(v.y >> 16));
            // z, w handled below to limit live h2 (reuse pattern)
            hs[q * 4 + 0] = __hadd2(hs[q * 4 + 0],
                                    e4m3x2_to_h2((unsigned short)(v.z & 0xffffu)));
            hs[q * 4 + 1] = __hadd2(hs[q * 4 + 1],
                                    e4m3x2_to_h2((unsigned short)(v.z >> 16)));
            hs[q * 4 + 2] = __hadd2(hs[q * 4 + 2],
                                    e4m3x2_to_h2((unsigned short)(v.w & 0xffffu)));
            hs[q * 4 + 3] = __hadd2(hs[q * 4 + 3],
                                    e4m3x2_to_h2((unsigned short)(v.w >> 16)));
        }
        // tree reduce 16 half2 partials
#pragma unroll
        for (int stp = 8; stp >= 1; stp >>= 1)
#pragma unroll
            for (int k = 0; k < 8; k++)
                if (k < stp) hs[k] = __hadd2(hs[k], hs[k + stp]);
        float2 f = __half22float2(hs[0]);
        float rsum = f.x + f.y;
        rsum += __shfl_xor_sync(0xffffffffu, rsum, 1);
        if ((tid & 1) == 0) atomicAdd(&g_u[bi + row], rsum);
    }
}

// ---------------- fused dual matvec: proven shape + half2 + load prefetch ---
template <bool RECIP>
__global__ __launch_bounds__(256) void dual_matvec_kernel(
    const float* __restrict__ a, const float* __restrict__ b,
    float* __restrict__ out_row, float* __restrict__ out_col) {
    const int ROWS = 64;
    const int tid = threadIdx.x;
    const int j = (blockIdx.x * 256 + tid) * 4;
    const int i0 = blockIdx.y * ROWS;
    __shared__ __half2 bsh[ROWS];
    __shared__ float rowpart[ROWS][9];
    const float a0 = a[0];
    const float b0 = b[0];
    if (tid < ROWS) {
        float v = b[i0 + tid];
        float w = RECIP ? (b0 / v) : (v / b0);
        bsh[tid] = __float2half2_rn(w);
    }
    __syncthreads();

    __half2 ah01, ah23;
    {
        float4 t = *reinterpret_cast<const float4*>(&a[j]);
        float x0 = RECIP ? (a0 / t.x) : (t.x / a0);
        float x1 = RECIP ? (a0 / t.y) : (t.y / a0);
        float x2 = RECIP ? (a0 / t.z) : (t.z / a0);
        float x3 = RECIP ? (a0 / t.w) : (t.w / a0);
        ah01 = __floats2half2_rn(x0, x1);
        ah23 = __floats2half2_rn(x2, x3);
    }
    float c0 = 0.f, c1 = 0.f, c2 = 0.f, c3 = 0.f;   // f32 column totals
    const int warp = tid >> 5, lane = tid & 31;
    const uint8_t* base = g_P0 + (size_t)i0 * NN + j;

    const __half2 zero2 = __floats2half2_rn(0.f, 0.f);
    uint32_t pu0 = ldg_u32_nc(base);
    uint32_t pu1 = ldg_u32_nc(base + NN);
#pragma unroll
    for (int chunk = 0; chunk < 2; chunk++) {       // 2 x 32-row chunks
        __half2 cacc01 = zero2, cacc23 = zero2;
#pragma unroll 4
        for (int it2 = 0; it2 < 16; it2++) {
            const int ii = chunk * 32 + it2 * 2;
            const uint32_t u0 = pu0;
            const uint32_t u1 = pu1;
            if (ii + 2 < ROWS) {   // prefetch next pair before compute
                pu0 = ldg_u32_nc(base + (size_t)(ii + 2) * NN);
                pu1 = ldg_u32_nc(base + (size_t)(ii + 3) * NN);
            }
            __half2 v0a = e4m3x2_to_h2((unsigned short)(u0 & 0xffffu));
            __half2 v0b = e4m3x2_to_h2((unsigned short)(u0 >> 16));
            __half2 v1a = e4m3x2_to_h2((unsigned short)(u1 & 0xffffu));
            __half2 v1b = e4m3x2_to_h2((unsigned short)(u1 >> 16));
            __half2 bb0 = bsh[ii], bb1 = bsh[ii + 1];
            cacc01 = __hfma2(v0a, bb0, cacc01);
            cacc23 = __hfma2(v0b, bb0, cacc23);
            cacc01 = __hfma2(v1a, bb1, cacc01);
            cacc23 = __hfma2(v1b, bb1, cacc23);
            __half2 d0 = __hfma2(v0b, ah23, __hmul2(v0a, ah01));
            __half2 d1 = __hfma2(v1b, ah23, __hmul2(v1a, ah01));
            __half2 lo = __halves2half2(__low2half(d0), __low2half(d1));
            __half2 hi = __halves2half2(__high2half(d0), __high2half(d1));
            __half2 dd = __hadd2(lo, hi);
#pragma unroll
            for (int o = 16; o > 0; o >>= 1)
                dd = __hadd2(dd, shfl_down_h2(dd, o));
            if (lane == 0) {
                rowpart[ii][warp] = __low2float(dd);
                rowpart[ii + 1][warp] = __high2float(dd);
            }
        }
        c0 += __low2float(cacc01); c1 += __high2float(cacc01);
        c2 += __low2float(cacc23); c3 += __high2float(cacc23);
    }
    __syncthreads();
    const float s_a = RECIP ? (1.0f / a0) : a0;
    const float s_b = RECIP ? (1.0f / b0) : b0;
    if (tid < ROWS) {
        float sacc = 0.f;
#pragma unroll
        for (int w = 0; w < 8; w++) sacc += rowpart[tid][w];
        atomicAdd(&out_row[i0 + tid], sacc * s_a);
    }
    atomicAdd(&out_col[j + 0], c0 * s_b);
    atomicAdd(&out_col[j + 1], c1 * s_b);
    atomicAdd(&out_col[j + 2], c2 * s_b);
    atomicAdd(&out_col[j + 3], c3 * s_b);
}

// colupd: r = 1/u (persists for CE), c/c2 two-step update from s/s2,
// then zero u,u2,s,s2 for next iteration / CE accumulators.
__global__ void colupd_kernel() {
    int i = blockIdx.x * blockDim.x + threadIdx.x;
    if (i < NN) {
        g_r[i] = 1.0f / g_u[i];
        g_r2[i] = 1.0f / g_u2[i];
        float cv = g_c[i], sv = g_s[i];
        cv *= fmaxf(BD / (cv * sv), 1.0f);
        cv *= fminf(BU / (cv * sv), 1.0f);
        g_c[i] = cv;
        float cv2 = g_c2[i], sv2 = g_s2[i];
        cv2 *= fmaxf(BD / (cv2 * sv2), 1.0f);
        cv2 *= fminf(BU / (cv2 * sv2), 1.0f);
        g_c2[i] = cv2;
        g_u[i] = 0.0f; g_u2[i] = 0.0f;
        g_s[i] = 0.0f; g_s2[i] = 0.0f;
    }
}

// ---------------- diag terms ----------------
__global__ __launch_bounds__(256) void diag_kernel(const int* __restrict__ labels) {
    int i = blockIdx.x * 256 + threadIdx.x;
    int lab = labels[i];
    float v1 = e4m3_byte_to_f32(g_P0[(size_t)i * NN + lab]);
    g_diag[i] = g_r[i] * v1 * g_c[lab];
    float v2 = e4m3_byte_to_f32(g_P0[(size_t)lab * NN + i]);
    g_diag2[i] = g_r2[i] * v2 * g_c2[lab];
}

// ---------------- fused CE: both logsumexps in ONE read of P0, half2 exp ----
__global__ __launch_bounds__(256) void ce_fused_kernel() {
    const int ROWS = 64;
    const int tid = threadIdx.x;
    const int j = (blockIdx.x * 256 + tid) * 4;
    const int i0 = blockIdx.y * ROWS;
    __shared__ __half2 Fsh[ROWS];   // r_i * c0
    __shared__ __half2 Csh[ROWS];   // c2_i / c2_0
    __shared__ float rowpart[ROWS][9];
    const float c0 = g_c[0];
    const float c20 = g_c2[0];
    if (tid < ROWS) {
        Fsh[tid] = __float2half2_rn(g_r[i0 + tid] * c0);
        Csh[tid] = __float2half2_rn(g_c2[i0 + tid] / c20);
    }
    __syncthreads();

    __half2 cn01, cn23, G01, G23;
    {
        float4 cv = *reinterpret_cast<const float4*>(&g_c[j]);
        float4 rv = *reinterpret_cast<const float4*>(&g_r2[j]);
        cn01 = __floats2half2_rn(cv.x / c0, cv.y / c0);
        cn23 = __floats2half2_rn(cv.z / c0, cv.w / c0);
        G01 = __floats2half2_rn(rv.x * c20, rv.y * c20);
        G23 = __floats2half2_rn(rv.z * c20, rv.w * c20);
    }
    const __half2 zero2 = __floats2half2_rn(0.f, 0.f);
    __half2 colacc01 = zero2, colacc23 = zero2;
    const int warp = tid >> 5, lane = tid & 31;
    const uint8_t* base = g_P0 + (size_t)i0 * NN + j;

    uint32_t pu0 = ldg_u32_nc(base);
    uint32_t pu1 = ldg_u32_nc(base + NN);
    for (int ii = 0; ii < ROWS; ii += 2) {
        const uint32_t u0 = pu0;
        const uint32_t u1 = pu1;
        if (ii + 2 < ROWS) {
            pu0 = ldg_u32_nc(base + (size_t)(ii + 2) * NN);
            pu1 = ldg_u32_nc(base + (size_t)(ii + 3) * NN);
        }
        __half2 v0a = e4m3x2_to_h2((unsigned short)(u0 & 0xffffu));
        __half2 v0b = e4m3x2_to_h2((unsigned short)(u0 >> 16));
        __half2 v1a = e4m3x2_to_h2((unsigned short)(u1 & 0xffffu));
        __half2 v1b = e4m3x2_to_h2((unsigned short)(u1 >> 16));
        __half2 F0 = Fsh[ii], F1 = Fsh[ii + 1];
        __half2 C0 = Csh[ii], C1 = Csh[ii + 1];
        __half2 x0 = __hadd2(h2exp(__hmul2(__hmul2(F0, cn01), v0a)),
                             h2exp(__hmul2(__hmul2(F0, cn23), v0b)));
        __half2 x1 = __hadd2(h2exp(__hmul2(__hmul2(F1, cn01), v1a)),
                             h2exp(__hmul2(__hmul2(F1, cn23), v1b)));
        colacc01 = __hadd2(colacc01, h2exp(__hmul2(__hmul2(G01, C0), v0a)));
        colacc23 = __hadd2(colacc23, h2exp(__hmul2(__hmul2(G23, C0), v0b)));
        colacc01 = __hadd2(colacc01, h2exp(__hmul2(__hmul2(G01, C1), v1a)));
        colacc23 = __hadd2(colacc23, h2exp(__hmul2(__hmul2(G23, C1), v1b)));
        __half2 lo = __halves2half2(__low2half(x0), __low2half(x1));
        __half2 hi = __halves2half2(__high2half(x0), __high2half(x1));
        __half2 dd = __hadd2(lo, hi);
#pragma unroll
        for (int o = 16; o > 0; o >>= 1)
            dd = __hadd2(dd, shfl_down_h2(dd, o));
        if (lane == 0) {
            rowpart[ii][warp] = __low2float(dd);
            rowpart[ii + 1][warp] = __high2float(dd);
        }
    }
    __syncthreads();
    if (tid < ROWS) {
        float sacc = 0.f;
#pragma unroll
        for (int w = 0; w < 8; w++) sacc += rowpart[tid][w];
        atomicAdd(&g_u[i0 + tid], sacc);
    }
    atomicAdd(&g_u2[j + 0], __low2float(colacc01));
    atomicAdd(&g_u2[j + 1], __high2float(colacc01));
    atomicAdd(&g_u2[j + 2], __low2float(colacc23));
    atomicAdd(&g_u2[j + 3], __high2float(colacc23));
}

__global__ __launch_bounds__(256) void ce_reduce_kernel() {
    int t = blockIdx.x * 256 + threadIdx.x;
    float v = (logf(g_u[t]) - g_diag[t]) + (logf(g_u2[t]) - g_diag2[t]);
    __shared__ float wsum[8];
#pragma unroll
    for (int o = 16; o > 0; o >>= 1)
        v += __shfl_down_sync(0xffffffffu, v, o);
    int warp = threadIdx.x >> 5, lane = threadIdx.x & 31;
    if (lane == 0) wsum[warp] = v;
    __syncthreads();
    if (threadIdx.x == 0) {
        float tt = 0.f;
#pragma unroll
        for (int w = 0; w < 8; w++) tt += wsum[w];
        atomicAdd(&g_sums[0], tt);
    }
}

__global__ void finalize_kernel(float* __restrict__ out) {
    out[0] = g_sums[0] / (2.0f * (float)NN);
}

// ---------------- launch ----------------
extern "C" void kernel_launch(void* const* d_in, const int* in_sizes, int n_in,
                              void* d_out, int out_size) {
    const float* A = (const float*)d_in[0];   // all_image_features [N, D]
    const float* B = (const float*)d_in[1];   // all_text_features  [N, D]
    const int* labels = (const int*)d_in[3];
    float* out = (float*)d_out;

    float *c, *c2, *u, *u2, *s, *s2;
    cudaGetSymbolAddress((void**)&c, g_c);
    cudaGetSymbolAddress((void**)&c2, g_c2);
    cudaGetSymbolAddress((void**)&u, g_u);
    cudaGetSymbolAddress((void**)&u2, g_u2);
    cudaGetSymbolAddress((void**)&s, g_s);
    cudaGetSymbolAddress((void**)&s2, g_s2);

    cudaFuncSetAttribute(gemm_i8_exp_kernel,
                         cudaFuncAttributeMaxDynamicSharedMemorySize,
                         2 * STAGE_BYTES);

    init_kernel<<<NN / 256, 256>>>();
    convert_kernel<<<NN * DD / 4 / 256, 256>>>(A, B);
    // GEMM epilogue also produces u = rowsum(P0), u2 = colsum(P0)
    // (== Sinkhorn iteration-1 pass1, since c = c2 = 1 initially)
    gemm_i8_exp_kernel<<<dim3(64, 64), 256, 2 * STAGE_BYTES>>>();

    for (int it = 0; it < 5; it++) {
        // pass2: s2_i += sum_j P0_ij (1/u2_j) ; s_j += sum_i P0_ij (1/u_i)
        dual_matvec_kernel<true><<<dim3(8, 128), 256>>>(u2, u, s2, s);
        colupd_kernel<<<NN / 256, 256>>>();
        if (it < 4) {
            // pass1: u_i += sum_j P0_ij c_j ; u2_j += sum_i P0_ij c2_i
            dual_matvec_kernel<false><<<dim3(8, 128), 256>>>(c, c2, u, u2);
        }
    }

    diag_kernel<<<NN / 256, 256>>>(labels);
    ce_fused_kernel<<<dim3(8, 128), 256>>>();
    ce_reduce_kernel<<<NN / 256, 256>>>();
    finalize_kernel<<<1, 1>>>(out);
}